// round 3
// baseline (speedup 1.0000x reference)
#include <cuda_runtime.h>
#include <cuda_bf16.h>
#include <math.h>
#include <stdint.h>

#define NN 8192
#define NB 1024
#define NM 256

// ---------------- device scratch (static, no allocation) ----------------
__device__ float g_z[128];
__device__ float g_v0[512];
__device__ float g_Ppsm[NM * 512];
__device__ float g_psmWhh[512 * 128];     // packed [j][r]
__device__ float g_Hseq[NM * 128];
__device__ float g_mps[NM * 128];
__device__ float g_POn[NN * 1024];
__device__ float g_POb[NB * 1024];
__device__ float g_POm[NM * 1024];
__device__ float g_PTb[NB * 1024];
__device__ float g_PTm[NM * 1024];
__device__ float g_preO[NN * 1024];        // [n][c][u][g] gate-interleaved
__device__ float g_preT[NB * 1024];        // [b][c][u][g]
__device__ float g_WhhO[8 * 64 * 128 * 4]; // [c][j4][rl][jj]
__device__ float g_WhhT[8 * 64 * 128 * 4];
__device__ float g_WseqO[8 * 128 * 11];    // [c*128+rl][k]
__device__ float g_WseqT[8 * 128 * 11];

__device__ __forceinline__ float sigm(float x) { return 1.0f / (1.0f + __expf(-x)); }
__device__ __forceinline__ float tanh_fast(float x) { return 2.0f / (1.0f + __expf(-2.0f * x)) - 1.0f; }

__device__ __forceinline__ uint32_t mapa_sh(uint32_t local_addr, uint32_t rank) {
    uint32_t remote;
    asm volatile("mapa.shared::cluster.u32 %0, %1, %2;" : "=r"(remote) : "r"(local_addr), "r"(rank));
    return remote;
}
__device__ __forceinline__ void stc_f32(uint32_t addr, float v) {
    asm volatile("st.shared::cluster.f32 [%0], %1;" :: "r"(addr), "f"(v) : "memory");
}
__device__ __forceinline__ void cluster_sync_all() {
    asm volatile("barrier.cluster.arrive.aligned;" ::: "memory");
    asm volatile("barrier.cluster.wait.aligned;" ::: "memory");
}

// ---------------- generic tiled GEMM: C[M][N] (+)= X[M][K] @ W[:, wofs:wofs+K]^T (+bias) ----
__global__ void k_gemm(const float* __restrict__ X, int ldx,
                       const float* __restrict__ W, int ldw, int wofs,
                       float* __restrict__ C, int M, int N, int K,
                       const float* __restrict__ bias, int accum)
{
    __shared__ float Xs[16][65];
    __shared__ float Ws[16][65];
    int tid = threadIdx.x;
    int tx = tid & 15, ty = tid >> 4;
    int n0 = blockIdx.x * 64, m0 = blockIdx.y * 64;
    float acc[4][4];
#pragma unroll
    for (int i = 0; i < 4; i++)
#pragma unroll
        for (int j = 0; j < 4; j++) acc[i][j] = 0.f;

    for (int k0 = 0; k0 < K; k0 += 16) {
        for (int i = tid; i < 1024; i += 256) {
            int mm = i >> 4, kk = i & 15;
            int k = k0 + kk;
            Xs[kk][mm] = (k < K) ? X[(size_t)(m0 + mm) * ldx + k] : 0.f;
            Ws[kk][mm] = (k < K) ? W[(size_t)(n0 + mm) * ldw + wofs + k] : 0.f;
        }
        __syncthreads();
#pragma unroll
        for (int kk = 0; kk < 16; kk++) {
            float a[4], b[4];
#pragma unroll
            for (int i = 0; i < 4; i++) a[i] = Xs[kk][ty * 4 + i];
#pragma unroll
            for (int j = 0; j < 4; j++) b[j] = Ws[kk][tx * 4 + j];
#pragma unroll
            for (int i = 0; i < 4; i++)
#pragma unroll
                for (int j = 0; j < 4; j++) acc[i][j] += a[i] * b[j];
        }
        __syncthreads();
    }
#pragma unroll
    for (int i = 0; i < 4; i++) {
        int m = m0 + ty * 4 + i;
#pragma unroll
        for (int j = 0; j < 4; j++) {
            int n = n0 + tx * 4 + j;
            float v = acc[i][j];
            if (bias) v += bias[n];
            size_t o = (size_t)m * N + n;
            if (accum) v += C[o];
            C[o] = v;
        }
    }
}

// ---------------- small prep kernels ----------------
__global__ void k_style(const float* __restrict__ perf, const float* __restrict__ sveW,
                        const float* __restrict__ sveb)
{
    int r = threadIdx.x; // 128
    float s = sveb[r];
    for (int k = 0; k < 64; k++) s += sveW[r * 64 + k] * perf[k];
    g_z[r] = fmaxf(s, 0.f);
}

__global__ void k_v0(const float* __restrict__ psmWih, const float* __restrict__ psmb)
{
    int r = threadIdx.x; // 512
    float s = psmb[r];
    for (int k = 0; k < 128; k++) s += psmWih[r * 384 + k] * g_z[k];
    g_v0[r] = s;
}

__global__ void k_pack_psm(const float* __restrict__ psmWhh)
{
    int idx = blockIdx.x * 256 + threadIdx.x; // 65536
    int r = idx & 511, j = idx >> 9;
    g_psmWhh[idx] = psmWhh[r * 128 + j];
}

__global__ void k_pack_whh(const float* __restrict__ whhO, const float* __restrict__ whhT)
{
    int idx = blockIdx.x * 256 + threadIdx.x; // 262144
    int jj = idx & 3, rl = (idx >> 2) & 127, j4 = (idx >> 9) & 63, c = idx >> 15;
    int grow = (rl >> 5) * 256 + c * 32 + (rl & 31);
    int col = j4 * 4 + jj;
    g_WhhO[idx] = whhO[grow * 256 + col];
    g_WhhT[idx] = whhT[grow * 256 + col];
}

__global__ void k_pack_wseq(const float* __restrict__ outWih, const float* __restrict__ tempoWih)
{
    int idx = blockIdx.x * 256 + threadIdx.x;
    if (idx >= 8 * 128 * 11) return;
    int k = idx % 11;
    int rc = idx / 11;              // c*128 + rl
    int rl = rc & 127, c = rc >> 7;
    int grow = (rl >> 5) * 256 + c * 32 + (rl & 31);
    g_WseqO[idx] = outWih[(size_t)grow * 1419 + 1280 + k];
    int col = (k == 0) ? 768 : (776 + k);
    g_WseqT[idx] = tempoWih[(size_t)grow * 915 + col];
}

// combine the three out-LSTM input projections into gate-interleaved preO
__global__ void k_combine_O()
{
    int idx = blockIdx.x * 256 + threadIdx.x;  // NN*1024
    int n = idx >> 10, grow = idx & 1023;
    int b = n >> 3, m = n >> 5;
    float v = g_POn[idx] + g_POb[b * 1024 + grow] + g_POm[m * 1024 + grow];
    int g = grow >> 8, c = (grow >> 5) & 7, uu = grow & 31;
    g_preO[(n << 10) + c * 128 + uu * 4 + g] = v;
}

__global__ void k_combine_T()
{
    int idx = blockIdx.x * 256 + threadIdx.x;  // NB*1024
    int bq = idx >> 10, grow = idx & 1023;
    int m = bq >> 2;
    float v = g_PTb[idx] + g_PTm[m * 1024 + grow];
    int g = grow >> 8, c = (grow >> 5) & 7, uu = grow & 31;
    g_preT[(bq << 10) + c * 128 + uu * 4 + g] = v;
}

// ---------------- psm LSTM over 256 measures (one CTA, 512 threads) ----------------
__global__ void __launch_bounds__(512, 1) k_psm_seq()
{
    __shared__ float h[128], cst[128];
    __shared__ float part[4][512];
    __shared__ float gate[512];
    int t = threadIdx.x;
    int a = t & 127, jg = t >> 7;
    if (t < 128) { h[t] = 0.f; cst[t] = 0.f; }
    __syncthreads();
    for (int m = 0; m < NM; m++) {
        float a0 = 0, a1 = 0, a2 = 0, a3 = 0;
#pragma unroll 4
        for (int jj = 0; jj < 32; jj++) {
            int j = jg * 32 + jj;
            float4 w = *(const float4*)(g_psmWhh + j * 512 + 4 * a);
            float hv = h[j];
            a0 += w.x * hv; a1 += w.y * hv; a2 += w.z * hv; a3 += w.w * hv;
        }
        part[jg][4 * a + 0] = a0; part[jg][4 * a + 1] = a1;
        part[jg][4 * a + 2] = a2; part[jg][4 * a + 3] = a3;
        __syncthreads();
        {
            float s = g_Ppsm[m * 512 + t] + g_v0[t];
#pragma unroll
            for (int gg = 0; gg < 4; gg++) s += part[gg][t];
            gate[t] = s;
        }
        __syncthreads();
        if (t < 128) {
            float cn = sigm(gate[128 + t]) * cst[t] + sigm(gate[t]) * tanhf(gate[256 + t]);
            cst[t] = cn;
            float hn = sigm(gate[384 + t]) * tanhf(cn);
            h[t] = hn;
            g_Hseq[m * 128 + t] = hn;
        }
        __syncthreads();
    }
}

// ---------------- sequential decoder: 8-CTA cluster, 512 thr/CTA ----------------
__global__ void __cluster_dims__(8, 1, 1) __launch_bounds__(512, 1)
k_seq(const float* __restrict__ fcW, const float* __restrict__ fcb,
      const float* __restrict__ tfcW, const float* __restrict__ tfcb,
      const float* __restrict__ attW, const float* __restrict__ attb,
      const float* __restrict__ attc, float* __restrict__ out)
{
    __shared__ float hbuf[2][256];
    __shared__ float thbuf[2][256];
    __shared__ float part[4][128];
    __shared__ float partT[4][128];
    __shared__ float WsO[128][11], WsT[128][11];
    __shared__ float fcw_s[10][32];
    __shared__ float tfc_s[32];
    __shared__ float attWs[10][10], attbs[10], attcs[10], fcbs[10];
    __shared__ float buf_s[8][10];
    __shared__ float prev_out_s[11];
    __shared__ float result_s[10];
    __shared__ float wsoft[8];
    __shared__ float hloc[32], thloc[32];
    __shared__ float pbuf[2][8][10];
    __shared__ float tpbuf[2][8];
    __shared__ float prevT_s, tfcb_s;

    const int t = threadIdx.x;
    uint32_t crank;
    asm("mov.u32 %0, %%cluster_ctarank;" : "=r"(crank));
    const int rl = t & 127, s = t >> 7;
    const int u = t & 31;
    const int wid = t >> 5;
    const int ci = (int)crank;

    // register-resident out-LSTM Whh slice: 64 weights / thread
    float w[64];
    {
        const float4* src = (const float4*)g_WhhO;
#pragma unroll
        for (int ii = 0; ii < 16; ii++) {
            float4 v = src[(ci * 64 + s * 16 + ii) * 128 + rl];
            w[4 * ii + 0] = v.x; w[4 * ii + 1] = v.y; w[4 * ii + 2] = v.z; w[4 * ii + 3] = v.w;
        }
    }
    if (t < 128) {
#pragma unroll
        for (int k = 0; k < 11; k++) {
            WsO[t][k] = g_WseqO[(ci * 128 + t) * 11 + k];
            WsT[t][k] = g_WseqT[(ci * 128 + t) * 11 + k];
        }
    }
    if (t < 320) fcw_s[wid][u] = fcW[wid * 256 + ci * 32 + u];
    if (t < 32)  tfc_s[t] = tfcW[ci * 32 + t];
    if (t < 256) { hbuf[0][t] = 0.f; hbuf[1][t] = 0.f; thbuf[0][t] = 0.f; thbuf[1][t] = 0.f; }
    if (t < 100) attWs[t / 10][t % 10] = attW[t];
    if (t < 10)  { attbs[t] = attb[t]; attcs[t] = attc[t]; fcbs[t] = fcb[t]; result_s[t] = 0.f; }
    if (t < 11)  prev_out_s[t] = 0.f;
    if (t < 80)  buf_s[t / 10][t % 10] = 0.f;
    if (t < 160) pbuf[t / 80][(t / 10) & 7][t % 10] = 0.f;
    if (t < 16)  tpbuf[t >> 3][t & 7] = 0.f;
    if (t == 0)  { tfcb_s = tfcb[0]; prevT_s = 0.f; }
    __syncthreads();
    cluster_sync_all();

    // precompute DSMEM remote bases
    uint32_t sb = (uint32_t)__cvta_generic_to_shared(&hbuf[0][0]);
    uint32_t off_th = (uint32_t)__cvta_generic_to_shared(&thbuf[0][0]) - sb;
    uint32_t off_pb = (uint32_t)__cvta_generic_to_shared(&pbuf[0][0][0]) - sb;
    uint32_t off_tp = (uint32_t)__cvta_generic_to_shared(&tpbuf[0][0]) - sb;
    uint32_t rb[8];
#pragma unroll
    for (int r = 0; r < 8; r++) rb[r] = mapa_sh(sb, (uint32_t)r);

    float cst = 0.f;   // out-LSTM cell (warp0 lanes)
    float tcst = 0.f;  // tempo cell   (warp1 lanes)
    float4 pvn = make_float4(0.f, 0.f, 0.f, 0.f);
    float4 pvTn = pvn;
    if (wid == 0) pvn  = *(const float4*)(g_preO + ci * 128 + 4 * u);
    if (wid == 1) pvTn = *(const float4*)(g_preT + ci * 128 + 4 * u);

    for (int n = 0; n < NN; n++) {
        const int b = n >> 3;
        const bool start = (n & 7) == 0;
        const int hq = (n + 1) & 1;       // write/read parity this step
        const int hp = n & 1;             // h read parity
        const int tp = (b & 1);
        const int tq = (b + 1) & 1;

        // ---- phase 1: matvec partials (+ prefetch next-step inputs) ----
        float4 pvc = make_float4(0.f, 0.f, 0.f, 0.f), pvTc = pvc;
        if (wid == 0) {
            pvc = pvn;
            int nn = (n + 1 < NN) ? n + 1 : n;
            pvn = *(const float4*)(g_preO + nn * 1024 + ci * 128 + 4 * u);
        }
        if (wid == 1 && start) {
            pvTc = pvTn;
            int bb = (b + 1 < NB) ? b + 1 : b;
            pvTn = *(const float4*)(g_preT + bb * 1024 + ci * 128 + 4 * u);
        }
        {
            float acc = 0.f;
            const float4* hb4 = (const float4*)hbuf[hp];
#pragma unroll
            for (int ii = 0; ii < 16; ii++) {
                float4 hv = hb4[s * 16 + ii];
                acc += w[4 * ii] * hv.x + w[4 * ii + 1] * hv.y + w[4 * ii + 2] * hv.z + w[4 * ii + 3] * hv.w;
            }
            part[s][rl] = acc;
        }
        if (start) {
            float accT = 0.f;
            const float4* wt4 = (const float4*)g_WhhT + (size_t)(ci * 64 + s * 16) * 128 + rl;
            const float4* th4 = (const float4*)thbuf[tp];
#pragma unroll
            for (int ii = 0; ii < 16; ii++) {
                float4 wv = wt4[(size_t)ii * 128];
                float4 hv = th4[s * 16 + ii];
                accT += wv.x * hv.x + wv.y * hv.y + wv.z * hv.z + wv.w * hv.w;
            }
            partT[s][rl] = accT;
        }
        __syncthreads();

        // ---- phase 2 ----
        if (wid == 0) {
            float gi = pvc.x, gf = pvc.y, gG = pvc.z, go = pvc.w;
#pragma unroll
            for (int s4 = 0; s4 < 4; s4++) {
                gi += part[s4][u];
                gf += part[s4][u + 32];
                gG += part[s4][u + 64];
                go += part[s4][u + 96];
            }
#pragma unroll
            for (int k = 0; k < 11; k++) {
                float pk = prev_out_s[k];
                gi += WsO[u][k] * pk;
                gf += WsO[u + 32][k] * pk;
                gG += WsO[u + 64][k] * pk;
                go += WsO[u + 96][k] * pk;
            }
            float cn = sigm(gf) * cst + sigm(gi) * tanh_fast(gG);
            cst = cn;
            float hn = sigm(go) * tanh_fast(cn);
            hloc[u] = hn;
            __syncwarp();
            float p = 0.f;
            if (u < 10) {
#pragma unroll
                for (int k = 0; k < 32; k++) p += fcw_s[u][k] * hloc[k];
            }
            uint32_t oh = (uint32_t)(hq * 256 + ci * 32 + u) * 4u;
#pragma unroll
            for (int r = 0; r < 8; r++) stc_f32(rb[r] + oh, hn);
            if (u < 10) {
                uint32_t op = off_pb + (uint32_t)(hq * 80 + ci * 10 + u) * 4u;
#pragma unroll
                for (int r = 0; r < 8; r++) stc_f32(rb[r] + op, p);
            }
        } else if (wid == 1 && start) {
            // attention over previous beat (cnt==8 always, except b==0 -> zeros)
            if (b > 0) {
                float sc = -1e30f;
                if (u < 8) {
                    sc = 0.f;
#pragma unroll
                    for (int j = 0; j < 10; j++) {
                        float a = attbs[j];
#pragma unroll
                        for (int k = 0; k < 10; k++) a += attWs[j][k] * buf_s[u][k];
                        sc += tanh_fast(a) * attcs[j];
                    }
                }
                float mx = sc;
#pragma unroll
                for (int off = 16; off; off >>= 1) mx = fmaxf(mx, __shfl_xor_sync(0xffffffffu, mx, off));
                float e = __expf(sc - mx);
                float sm = e;
#pragma unroll
                for (int off = 16; off; off >>= 1) sm += __shfl_xor_sync(0xffffffffu, sm, off);
                if (u < 8) wsoft[u] = e / sm;
                __syncwarp();
                if (u < 10) {
                    float r = 0.f;
#pragma unroll
                    for (int p = 0; p < 8; p++) r += wsoft[p] * buf_s[p][u];
                    result_s[u] = r;
                }
            } else {
                if (u < 10) result_s[u] = 0.f;
            }
            __syncwarp();
            float gi = pvTc.x, gf = pvTc.y, gG = pvTc.z, go = pvTc.w;
#pragma unroll
            for (int s4 = 0; s4 < 4; s4++) {
                gi += partT[s4][u];
                gf += partT[s4][u + 32];
                gG += partT[s4][u + 64];
                go += partT[s4][u + 96];
            }
            {
                float p0 = prevT_s;
                gi += WsT[u][0] * p0;
                gf += WsT[u + 32][0] * p0;
                gG += WsT[u + 64][0] * p0;
                go += WsT[u + 96][0] * p0;
            }
#pragma unroll
            for (int k = 0; k < 10; k++) {
                float rk = result_s[k];
                gi += WsT[u][1 + k] * rk;
                gf += WsT[u + 32][1 + k] * rk;
                gG += WsT[u + 64][1 + k] * rk;
                go += WsT[u + 96][1 + k] * rk;
            }
            float cn = sigm(gf) * tcst + sigm(gi) * tanh_fast(gG);
            tcst = cn;
            float hn = sigm(go) * tanh_fast(cn);
            thloc[u] = hn;
            __syncwarp();
            uint32_t ot = off_th + (uint32_t)(tq * 256 + ci * 32 + u) * 4u;
#pragma unroll
            for (int r = 0; r < 8; r++) stc_f32(rb[r] + ot, hn);
            if (u == 0) {
                float tpv = 0.f;
#pragma unroll
                for (int k = 0; k < 32; k++) tpv += tfc_s[k] * thloc[k];
                uint32_t oq = off_tp + (uint32_t)(tq * 8 + ci) * 4u;
#pragma unroll
                for (int r = 0; r < 8; r++) stc_f32(rb[r] + oq, tpv);
            }
        }
        cluster_sync_all();

        // ---- phase 3: tiny epilogue (redundant per CTA) ----
        if (t < 10) {
            float o = fcbs[t];
#pragma unroll
            for (int c = 0; c < 8; c++) o += pbuf[hq][c][t];
            buf_s[n & 7][t] = o;
            prev_out_s[t + 1] = o;
            if (ci == 0) out[n * 11 + 1 + t] = o;
        }
        if (t == 10) {
            float tv = prevT_s;
            if (start) {
                tv = tfcb_s;
#pragma unroll
                for (int c = 0; c < 8; c++) tv += tpbuf[tq][c];
                prevT_s = tv;
            }
            prev_out_s[0] = tv;
            if (ci == 0) out[n * 11] = tv;
        }
        __syncthreads();
    }
}

// ---------------- host launcher ----------------
extern "C" void kernel_launch(void* const* d_in, const int* in_sizes, int n_in,
                              void* d_out, int out_size)
{
    const float* note     = (const float*)d_in[0];
    const float* beat     = (const float*)d_in[1];
    const float* meas     = (const float*)d_in[2];
    const float* perf     = (const float*)d_in[3];
    const float* res      = (const float*)d_in[4];
    const float* sveW     = (const float*)d_in[5];
    const float* sveb     = (const float*)d_in[6];
    const float* psmWih   = (const float*)d_in[7];
    const float* psmWhh   = (const float*)d_in[8];
    const float* psmb     = (const float*)d_in[9];
    const float* mpfW     = (const float*)d_in[10];
    const float* mpfb     = (const float*)d_in[11];
    const float* attW     = (const float*)d_in[12];
    const float* attb     = (const float*)d_in[13];
    const float* attc     = (const float*)d_in[14];
    const float* tempoWih = (const float*)d_in[15];
    const float* tempoWhh = (const float*)d_in[16];
    const float* tempob   = (const float*)d_in[17];
    const float* tfcW     = (const float*)d_in[18];
    const float* tfcb     = (const float*)d_in[19];
    const float* outWih   = (const float*)d_in[20];
    const float* outWhh   = (const float*)d_in[21];
    const float* outb     = (const float*)d_in[22];
    const float* fcW      = (const float*)d_in[23];
    const float* fcb      = (const float*)d_in[24];

    float *Ppsm, *Hseq, *mps, *POn, *POb, *POm, *PTb, *PTm;
    cudaGetSymbolAddress((void**)&Ppsm, g_Ppsm);
    cudaGetSymbolAddress((void**)&Hseq, g_Hseq);
    cudaGetSymbolAddress((void**)&mps,  g_mps);
    cudaGetSymbolAddress((void**)&POn,  g_POn);
    cudaGetSymbolAddress((void**)&POb,  g_POb);
    cudaGetSymbolAddress((void**)&POm,  g_POm);
    cudaGetSymbolAddress((void**)&PTb,  g_PTb);
    cudaGetSymbolAddress((void**)&PTm,  g_PTm);

    k_style<<<1, 128>>>(perf, sveW, sveb);
    k_v0<<<1, 512>>>(psmWih, psmb);
    k_pack_whh<<<1024, 256>>>(outWhh, tempoWhh);
    k_pack_wseq<<<44, 256>>>(outWih, tempoWih);
    k_pack_psm<<<256, 256>>>(psmWhh);

    // psm input projection + psm LSTM + mps
    k_gemm<<<dim3(8, 4), 256>>>(meas, 256, psmWih, 384, 128, Ppsm, 256, 512, 256, nullptr, 0);
    k_psm_seq<<<1, 512>>>();
    k_gemm<<<dim3(2, 4), 256>>>(Hseq, 128, mpfW, 128, 0, mps, 256, 128, 128, mpfb, 0);

    // out-LSTM input projections
    k_gemm<<<dim3(16, 128), 256>>>(note, 512, outWih, 1419, 0,    POn, NN, 1024, 512, nullptr, 0);
    k_gemm<<<dim3(16, 16),  256>>>(beat, 512, outWih, 1419, 512,  POb, NB, 1024, 512, nullptr, 0);
    k_gemm<<<dim3(16, 4),   256>>>(meas, 256, outWih, 1419, 1024, POm, NM, 1024, 256, outb,    0);
    k_gemm<<<dim3(16, 4),   256>>>(mps,  128, outWih, 1419, 1291, POm, NM, 1024, 128, nullptr, 1);

    // tempo-LSTM input projections
    k_gemm<<<dim3(16, 16), 256>>>(beat, 512, tempoWih, 915, 0,   PTb, NB, 1024, 512, tempob,  0);
    k_gemm<<<dim3(16, 16), 256>>>(res,  8,   tempoWih, 915, 769, PTb, NB, 1024, 8,   nullptr, 1);
    k_gemm<<<dim3(16, 4),  256>>>(meas, 256, tempoWih, 915, 512, PTm, NM, 1024, 256, nullptr, 0);
    k_gemm<<<dim3(16, 4),  256>>>(mps,  128, tempoWih, 915, 787, PTm, NM, 1024, 128, nullptr, 1);

    // pre-combine gate inputs
    k_combine_O<<<NN * 4, 256>>>();
    k_combine_T<<<NB * 4, 256>>>();

    // sequential decoder
    k_seq<<<8, 512>>>(fcW, fcb, tfcW, tfcb, attW, attb, attc, (float*)d_out);
}

// round 4
// speedup vs baseline: 1.0816x; 1.0816x over previous
#include <cuda_runtime.h>
#include <cuda_bf16.h>
#include <math.h>
#include <stdint.h>

#define NN 8192
#define NB 1024
#define NM 256

// ---------------- device scratch (static, no allocation) ----------------
__device__ float g_z[128];
__device__ float g_v0[512];
__device__ float g_Ppsm[NM * 512];
__device__ float g_psmWhh[512 * 128];     // packed [j][r]
__device__ float g_Hseq[NM * 128];
__device__ float g_mps[NM * 128];
__device__ float g_POn[NN * 1024];
__device__ float g_POb[NB * 1024];
__device__ float g_POm[NM * 1024];
__device__ float g_PTb[NB * 1024];
__device__ float g_PTm[NM * 1024];
__device__ float g_preO[NN * 1024];        // [n][c][u][g] gate-interleaved
__device__ float g_preT[NB * 1024];        // [b][c][u][g]
__device__ __align__(16) float g_WhhO[8 * 64 * 128 * 4]; // [c][j4][rl][jj]
__device__ __align__(16) float g_WhhT[8 * 64 * 128 * 4];
__device__ float g_WseqO[8 * 128 * 11];    // [c*128+rl][k]
__device__ float g_WseqT[8 * 128 * 11];

__device__ __forceinline__ float sigm(float x) { return 1.0f / (1.0f + __expf(-x)); }
__device__ __forceinline__ float tanh_fast(float x) { return 2.0f / (1.0f + __expf(-2.0f * x)) - 1.0f; }

__device__ __forceinline__ uint32_t mapa_sh(uint32_t local_addr, uint32_t rank) {
    uint32_t remote;
    asm volatile("mapa.shared::cluster.u32 %0, %1, %2;" : "=r"(remote) : "r"(local_addr), "r"(rank));
    return remote;
}
__device__ __forceinline__ void cluster_sync_all() {
    asm volatile("barrier.cluster.arrive.aligned;" ::: "memory");
    asm volatile("barrier.cluster.wait.aligned;" ::: "memory");
}
__device__ __forceinline__ void st_async_b64(uint32_t raddr, uint64_t v, uint32_t rmbar) {
    asm volatile("st.async.weak.shared::cluster.mbarrier::complete_tx::bytes.b64 [%0], %1, [%2];"
                 :: "r"(raddr), "l"(v), "r"(rmbar) : "memory");
}
__device__ __forceinline__ void st_async_b32(uint32_t raddr, uint32_t v, uint32_t rmbar) {
    asm volatile("st.async.weak.shared::cluster.mbarrier::complete_tx::bytes.b32 [%0], %1, [%2];"
                 :: "r"(raddr), "r"(v), "r"(rmbar) : "memory");
}
__device__ __forceinline__ void mbar_init(uint32_t mb, uint32_t cnt) {
    asm volatile("mbarrier.init.shared.b64 [%0], %1;" :: "r"(mb), "r"(cnt) : "memory");
}
__device__ __forceinline__ void mbar_expect(uint32_t mb, uint32_t tx) {
    asm volatile("mbarrier.arrive.expect_tx.shared.b64 _, [%0], %1;" :: "r"(mb), "r"(tx) : "memory");
}
__device__ __forceinline__ void mbar_wait(uint32_t mb, uint32_t ph) {
    asm volatile(
        "{\n\t.reg .pred P;\n"
        "LW_%=:\n\t"
        "mbarrier.try_wait.parity.acquire.cluster.shared::cta.b64 P, [%0], %1, 0x989680;\n\t"
        "@P bra LD_%=;\n\t"
        "bra LW_%=;\n"
        "LD_%=:\n\t}"
        :: "r"(mb), "r"(ph) : "memory");
}
__device__ __forceinline__ uint64_t pk2(float x, float y) {
    uint64_t r; asm("mov.b64 %0, {%1, %2};" : "=l"(r) : "f"(x), "f"(y)); return r;
}
__device__ __forceinline__ void ffma2(uint64_t& acc, uint64_t a, uint64_t b) {
    asm("fma.rn.f32x2 %0, %1, %2, %0;" : "+l"(acc) : "l"(a), "l"(b));
}
__device__ __forceinline__ float upk_sum(uint64_t a) {
    float lo, hi; asm("mov.b64 {%0, %1}, %2;" : "=f"(lo), "=f"(hi) : "l"(a)); return lo + hi;
}
__device__ __forceinline__ uint64_t d2u(double d) { return __double_as_longlong(d); }

// ---------------- generic tiled GEMM: C[M][N] (+)= X[M][K] @ W[:, wofs:wofs+K]^T (+bias) ----
__global__ void k_gemm(const float* __restrict__ X, int ldx,
                       const float* __restrict__ W, int ldw, int wofs,
                       float* __restrict__ C, int M, int N, int K,
                       const float* __restrict__ bias, int accum)
{
    __shared__ float Xs[16][65];
    __shared__ float Ws[16][65];
    int tid = threadIdx.x;
    int tx = tid & 15, ty = tid >> 4;
    int n0 = blockIdx.x * 64, m0 = blockIdx.y * 64;
    float acc[4][4];
#pragma unroll
    for (int i = 0; i < 4; i++)
#pragma unroll
        for (int j = 0; j < 4; j++) acc[i][j] = 0.f;

    for (int k0 = 0; k0 < K; k0 += 16) {
        for (int i = tid; i < 1024; i += 256) {
            int mm = i >> 4, kk = i & 15;
            int k = k0 + kk;
            Xs[kk][mm] = (k < K) ? X[(size_t)(m0 + mm) * ldx + k] : 0.f;
            Ws[kk][mm] = (k < K) ? W[(size_t)(n0 + mm) * ldw + wofs + k] : 0.f;
        }
        __syncthreads();
#pragma unroll
        for (int kk = 0; kk < 16; kk++) {
            float a[4], b[4];
#pragma unroll
            for (int i = 0; i < 4; i++) a[i] = Xs[kk][ty * 4 + i];
#pragma unroll
            for (int j = 0; j < 4; j++) b[j] = Ws[kk][tx * 4 + j];
#pragma unroll
            for (int i = 0; i < 4; i++)
#pragma unroll
                for (int j = 0; j < 4; j++) acc[i][j] += a[i] * b[j];
        }
        __syncthreads();
    }
#pragma unroll
    for (int i = 0; i < 4; i++) {
        int m = m0 + ty * 4 + i;
#pragma unroll
        for (int j = 0; j < 4; j++) {
            int n = n0 + tx * 4 + j;
            float v = acc[i][j];
            if (bias) v += bias[n];
            size_t o = (size_t)m * N + n;
            if (accum) v += C[o];
            C[o] = v;
        }
    }
}

// ---------------- small prep kernels ----------------
__global__ void k_style(const float* __restrict__ perf, const float* __restrict__ sveW,
                        const float* __restrict__ sveb)
{
    int r = threadIdx.x; // 128
    float s = sveb[r];
    for (int k = 0; k < 64; k++) s += sveW[r * 64 + k] * perf[k];
    g_z[r] = fmaxf(s, 0.f);
}

__global__ void k_v0(const float* __restrict__ psmWih, const float* __restrict__ psmb)
{
    int r = threadIdx.x; // 512
    float s = psmb[r];
    for (int k = 0; k < 128; k++) s += psmWih[r * 384 + k] * g_z[k];
    g_v0[r] = s;
}

__global__ void k_pack_psm(const float* __restrict__ psmWhh)
{
    int idx = blockIdx.x * 256 + threadIdx.x; // 65536
    int r = idx & 511, j = idx >> 9;
    g_psmWhh[idx] = psmWhh[r * 128 + j];
}

__global__ void k_pack_whh(const float* __restrict__ whhO, const float* __restrict__ whhT)
{
    int idx = blockIdx.x * 256 + threadIdx.x; // 262144
    int jj = idx & 3, rl = (idx >> 2) & 127, j4 = (idx >> 9) & 63, c = idx >> 15;
    int grow = (rl >> 5) * 256 + c * 32 + (rl & 31);
    int col = j4 * 4 + jj;
    g_WhhO[idx] = whhO[grow * 256 + col];
    g_WhhT[idx] = whhT[grow * 256 + col];
}

__global__ void k_pack_wseq(const float* __restrict__ outWih, const float* __restrict__ tempoWih)
{
    int idx = blockIdx.x * 256 + threadIdx.x;
    if (idx >= 8 * 128 * 11) return;
    int k = idx % 11;
    int rc = idx / 11;              // c*128 + rl
    int rl = rc & 127, c = rc >> 7;
    int grow = (rl >> 5) * 256 + c * 32 + (rl & 31);
    g_WseqO[idx] = outWih[(size_t)grow * 1419 + 1280 + k];
    int col = (k == 0) ? 768 : (776 + k);
    g_WseqT[idx] = tempoWih[(size_t)grow * 915 + col];
}

// combine the three out-LSTM input projections into gate-interleaved preO
__global__ void k_combine_O()
{
    int idx = blockIdx.x * 256 + threadIdx.x;  // NN*1024
    int n = idx >> 10, grow = idx & 1023;
    int b = n >> 3, m = n >> 5;
    float v = g_POn[idx] + g_POb[b * 1024 + grow] + g_POm[m * 1024 + grow];
    int g = grow >> 8, c = (grow >> 5) & 7, uu = grow & 31;
    g_preO[(n << 10) + c * 128 + uu * 4 + g] = v;
}

__global__ void k_combine_T()
{
    int idx = blockIdx.x * 256 + threadIdx.x;  // NB*1024
    int bq = idx >> 10, grow = idx & 1023;
    int m = bq >> 2;
    float v = g_PTb[idx] + g_PTm[m * 1024 + grow];
    int g = grow >> 8, c = (grow >> 5) & 7, uu = grow & 31;
    g_preT[(bq << 10) + c * 128 + uu * 4 + g] = v;
}

// ---------------- psm LSTM over 256 measures (one CTA, 512 threads) ----------------
__global__ void __launch_bounds__(512, 1) k_psm_seq()
{
    __shared__ float h[128], cst[128];
    __shared__ float part[4][512];
    __shared__ float gate[512];
    int t = threadIdx.x;
    int a = t & 127, jg = t >> 7;
    if (t < 128) { h[t] = 0.f; cst[t] = 0.f; }
    __syncthreads();
    for (int m = 0; m < NM; m++) {
        float a0 = 0, a1 = 0, a2 = 0, a3 = 0;
#pragma unroll 4
        for (int jj = 0; jj < 32; jj++) {
            int j = jg * 32 + jj;
            float4 w = *(const float4*)(g_psmWhh + j * 512 + 4 * a);
            float hv = h[j];
            a0 += w.x * hv; a1 += w.y * hv; a2 += w.z * hv; a3 += w.w * hv;
        }
        part[jg][4 * a + 0] = a0; part[jg][4 * a + 1] = a1;
        part[jg][4 * a + 2] = a2; part[jg][4 * a + 3] = a3;
        __syncthreads();
        {
            float s = g_Ppsm[m * 512 + t] + g_v0[t];
#pragma unroll
            for (int gg = 0; gg < 4; gg++) s += part[gg][t];
            gate[t] = s;
        }
        __syncthreads();
        if (t < 128) {
            float cn = sigm(gate[128 + t]) * cst[t] + sigm(gate[t]) * tanhf(gate[256 + t]);
            cst[t] = cn;
            float hn = sigm(gate[384 + t]) * tanhf(cn);
            h[t] = hn;
            g_Hseq[m * 128 + t] = hn;
        }
        __syncthreads();
    }
}

// ---------------- sequential decoder: 8-CTA cluster, 256 thr/CTA, mbarrier sync ----------------
__global__ void __cluster_dims__(8, 1, 1) __launch_bounds__(256, 1)
k_seq(const float* __restrict__ fcW, const float* __restrict__ fcb,
      const float* __restrict__ tfcW, const float* __restrict__ tfcb,
      const float* __restrict__ attW, const float* __restrict__ attb,
      const float* __restrict__ attc, float* __restrict__ out)
{
    extern __shared__ double2 WhhT_sm[];              // 64*128 double2 per CTA = 128 KB

    __shared__ __align__(16) float hbuf[2][256];
    __shared__ __align__(16) float thbuf[2][256];
    __shared__ __align__(16) float part[2][128];
    __shared__ __align__(16) float partT[2][128];
    __shared__ float WsO[128][11], WsT[128][11];
    __shared__ float fcw_s[10][32];
    __shared__ float tfc_s[32];
    __shared__ float attWs[10][10], attbs[10], attcs[10], fcbs[10];
    __shared__ float buf_s[8][10];
    __shared__ float prev_out_s[11];
    __shared__ float result_s[10];
    __shared__ float wsoft[8];
    __shared__ float hloc[32], thloc[32];
    __shared__ __align__(8) float pbuf[2][8][12];     // 12-padded rows for b64 alignment
    __shared__ float tpbuf[2][8];
    __shared__ float prevT_s, tfcb_s;
    __shared__ __align__(8) uint64_t mbar_s[2];

    const int t = threadIdx.x;
    uint32_t crank;
    asm("mov.u32 %0, %%cluster_ctarank;" : "=r"(crank));
    const int rl = t & 127, s = t >> 7;       // s in {0,1}: k-half
    const int u = t & 31;
    const int wid = t >> 5;
    const int ci = (int)crank;

    // ---- register-resident out-LSTM Whh slice: 128 weights/thread as 32 double2 ----
    double2 wreg[32];
    {
        const double2* src = (const double2*)g_WhhO;
#pragma unroll
        for (int ii = 0; ii < 32; ii++)
            wreg[ii] = src[(size_t)(ci * 64 + s * 32 + ii) * 128 + rl];
    }
    // ---- tempo Whh slice into dynamic smem (same layout) ----
    {
        const double2* src = (const double2*)g_WhhT;
        for (int i = t; i < 8192; i += 256)
            WhhT_sm[i] = src[(size_t)ci * 8192 + i];
    }
    if (t < 128) {
#pragma unroll
        for (int k = 0; k < 11; k++) {
            WsO[t][k] = g_WseqO[(ci * 128 + t) * 11 + k];
            WsT[t][k] = g_WseqT[(ci * 128 + t) * 11 + k];
        }
    }
    for (int i = t; i < 320; i += 256) fcw_s[i >> 5][i & 31] = fcW[(i >> 5) * 256 + ci * 32 + (i & 31)];
    if (t < 32)  tfc_s[t] = tfcW[ci * 32 + t];
    if (t < 256) { hbuf[0][t] = 0.f; hbuf[1][t] = 0.f; thbuf[0][t] = 0.f; thbuf[1][t] = 0.f; }
    if (t < 100) attWs[t / 10][t % 10] = attW[t];
    if (t < 10)  { attbs[t] = attb[t]; attcs[t] = attc[t]; fcbs[t] = fcb[t]; result_s[t] = 0.f; }
    if (t < 11)  prev_out_s[t] = 0.f;
    if (t < 80)  buf_s[t / 10][t % 10] = 0.f;
    for (int i = t; i < 192; i += 256) pbuf[i / 96][(i / 12) & 7][i % 12] = 0.f;
    if (t < 16)  tpbuf[t >> 3][t & 7] = 0.f;
    if (t == 0)  { tfcb_s = tfcb[0]; prevT_s = 0.f; }

    const uint32_t sb = (uint32_t)__cvta_generic_to_shared(&hbuf[0][0]);
    const uint32_t off_th = (uint32_t)__cvta_generic_to_shared(&thbuf[0][0]) - sb;
    const uint32_t off_pb = (uint32_t)__cvta_generic_to_shared(&pbuf[0][0][0]) - sb;
    const uint32_t off_tp = (uint32_t)__cvta_generic_to_shared(&tpbuf[0][0]) - sb;
    const uint32_t off_mb = (uint32_t)__cvta_generic_to_shared(&mbar_s[0]) - sb;
    const uint32_t lmb0 = sb + off_mb;

    if (t == 0) { mbar_init(lmb0, 1); mbar_init(lmb0 + 8, 1); }
    __syncthreads();
    cluster_sync_all();   // one-time: mbar init + smem staging visible cluster-wide

    uint32_t rb[8];
#pragma unroll
    for (int r = 0; r < 8; r++) rb[r] = mapa_sh(sb, (uint32_t)r);

    float cst = 0.f;   // out-LSTM cell (warp0 lanes)
    float tcst = 0.f;  // tempo cell   (warp1 lanes)
    float4 pvn = make_float4(0.f, 0.f, 0.f, 0.f);
    float4 pvTn = pvn;
    if (wid == 0) pvn  = *(const float4*)(g_preO + ci * 128 + 4 * u);
    if (wid == 1) pvTn = *(const float4*)(g_preT + ci * 128 + 4 * u);

    const uint32_t EXP_NS = 8 * 32 * 4 + 8 * 10 * 4;              // 1344
    const uint32_t EXP_S  = EXP_NS + 8 * 32 * 4 + 8 * 4;          // 2400

    for (int n = 0; n < NN; n++) {
        const int b = n >> 3;
        const bool start = (n & 7) == 0;
        const int hq = (n + 1) & 1;       // write parity this step
        const int hp = n & 1;             // h read parity
        const int tp = (b & 1);
        const int tq = (b + 1) & 1;
        const uint32_t mb8 = (uint32_t)(n & 1) * 8u;

        // ---- arm local barrier for this step ----
        if (t == 0) mbar_expect(lmb0 + mb8, start ? EXP_S : EXP_NS);

        // ---- phase 1: matvec partials (+ prefetch next-step inputs) ----
        float4 pvc = make_float4(0.f, 0.f, 0.f, 0.f), pvTc = pvc;
        if (wid == 0) {
            pvc = pvn;
            int nn = (n + 1 < NN) ? n + 1 : n;
            pvn = *(const float4*)(g_preO + nn * 1024 + ci * 128 + 4 * u);
        }
        if (wid == 1 && start) {
            pvTc = pvTn;
            int bb = (b + 1 < NB) ? b + 1 : b;
            pvTn = *(const float4*)(g_preT + bb * 1024 + ci * 128 + 4 * u);
        }
        {
            const double2* hb2 = (const double2*)hbuf[hp];
            uint64_t A0 = 0ull, A1 = 0ull, A2 = 0ull, A3 = 0ull;
#pragma unroll
            for (int ii = 0; ii < 32; ii += 2) {
                double2 h0 = hb2[s * 32 + ii];
                double2 h1 = hb2[s * 32 + ii + 1];
                ffma2(A0, d2u(wreg[ii].x), d2u(h0.x));
                ffma2(A1, d2u(wreg[ii].y), d2u(h0.y));
                ffma2(A2, d2u(wreg[ii + 1].x), d2u(h1.x));
                ffma2(A3, d2u(wreg[ii + 1].y), d2u(h1.y));
            }
            part[s][rl] = upk_sum(A0) + upk_sum(A1) + upk_sum(A2) + upk_sum(A3);
        }
        if (start) {
            const double2* hb2 = (const double2*)thbuf[tp];
            uint64_t A0 = 0ull, A1 = 0ull;
#pragma unroll 8
            for (int ii = 0; ii < 32; ii++) {
                double2 wv = WhhT_sm[(s * 32 + ii) * 128 + rl];
                double2 hv = hb2[s * 32 + ii];
                ffma2(A0, d2u(wv.x), d2u(hv.x));
                ffma2(A1, d2u(wv.y), d2u(hv.y));
            }
            partT[s][rl] = upk_sum(A0) + upk_sum(A1);
        }
        __syncthreads();

        // ---- phase 2 ----
        if (wid == 0) {
            float gi = pvc.x + part[0][u]      + part[1][u];
            float gf = pvc.y + part[0][u + 32] + part[1][u + 32];
            float gG = pvc.z + part[0][u + 64] + part[1][u + 64];
            float go = pvc.w + part[0][u + 96] + part[1][u + 96];
#pragma unroll
            for (int k = 0; k < 11; k++) {
                float pk = prev_out_s[k];
                gi += WsO[u][k] * pk;
                gf += WsO[u + 32][k] * pk;
                gG += WsO[u + 64][k] * pk;
                go += WsO[u + 96][k] * pk;
            }
            float cn = sigm(gf) * cst + sigm(gi) * tanh_fast(gG);
            cst = cn;
            float hn = sigm(go) * tanh_fast(cn);
            hloc[u] = hn;
            __syncwarp();
            float p = 0.f;
            if (u < 10) {
#pragma unroll
                for (int k = 0; k < 32; k++) p += fcw_s[u][k] * hloc[k];
            }
            float hnx = __shfl_down_sync(0xffffffffu, hn, 1);
            if (!(u & 1)) {
                uint64_t hv2 = pk2(hn, hnx);
                uint32_t dof = (uint32_t)(hq * 256 + ci * 32 + u) * 4u;
#pragma unroll
                for (int r = 0; r < 8; r++) st_async_b64(rb[r] + dof, hv2, rb[r] + off_mb + mb8);
            }
            float pa = __shfl_sync(0xffffffffu, p, 2 * u);
            float pb_ = __shfl_sync(0xffffffffu, p, 2 * u + 1);
            if (u < 5) {
                uint64_t pv2 = pk2(pa, pb_);
                uint32_t dof = off_pb + (uint32_t)(hq * 96 + ci * 12 + 2 * u) * 4u;
#pragma unroll
                for (int r = 0; r < 8; r++) st_async_b64(rb[r] + dof, pv2, rb[r] + off_mb + mb8);
            }
        } else if (wid == 1 && start) {
            // attention over previous beat
            if (b > 0) {
                float sc = -1e30f;
                if (u < 8) {
                    sc = 0.f;
#pragma unroll
                    for (int j = 0; j < 10; j++) {
                        float a = attbs[j];
#pragma unroll
                        for (int k = 0; k < 10; k++) a += attWs[j][k] * buf_s[u][k];
                        sc += tanh_fast(a) * attcs[j];
                    }
                }
                float mx = sc;
#pragma unroll
                for (int off = 16; off; off >>= 1) mx = fmaxf(mx, __shfl_xor_sync(0xffffffffu, mx, off));
                float e = __expf(sc - mx);
                float sm = e;
#pragma unroll
                for (int off = 16; off; off >>= 1) sm += __shfl_xor_sync(0xffffffffu, sm, off);
                if (u < 8) wsoft[u] = e / sm;
                __syncwarp();
                if (u < 10) {
                    float r = 0.f;
#pragma unroll
                    for (int p = 0; p < 8; p++) r += wsoft[p] * buf_s[p][u];
                    result_s[u] = r;
                }
            } else {
                if (u < 10) result_s[u] = 0.f;
            }
            __syncwarp();
            float gi = pvTc.x + partT[0][u]      + partT[1][u];
            float gf = pvTc.y + partT[0][u + 32] + partT[1][u + 32];
            float gG = pvTc.z + partT[0][u + 64] + partT[1][u + 64];
            float go = pvTc.w + partT[0][u + 96] + partT[1][u + 96];
            {
                float p0 = prevT_s;
                gi += WsT[u][0] * p0;
                gf += WsT[u + 32][0] * p0;
                gG += WsT[u + 64][0] * p0;
                go += WsT[u + 96][0] * p0;
            }
#pragma unroll
            for (int k = 0; k < 10; k++) {
                float rk = result_s[k];
                gi += WsT[u][1 + k] * rk;
                gf += WsT[u + 32][1 + k] * rk;
                gG += WsT[u + 64][1 + k] * rk;
                go += WsT[u + 96][1 + k] * rk;
            }
            float cn = sigm(gf) * tcst + sigm(gi) * tanh_fast(gG);
            tcst = cn;
            float hn = sigm(go) * tanh_fast(cn);
            thloc[u] = hn;
            __syncwarp();
            float hnx = __shfl_down_sync(0xffffffffu, hn, 1);
            if (!(u & 1)) {
                uint64_t hv2 = pk2(hn, hnx);
                uint32_t dof = off_th + (uint32_t)(tq * 256 + ci * 32 + u) * 4u;
#pragma unroll
                for (int r = 0; r < 8; r++) st_async_b64(rb[r] + dof, hv2, rb[r] + off_mb + mb8);
            }
            if (u == 0) {
                float tpv = 0.f;
#pragma unroll
                for (int k = 0; k < 32; k++) tpv += tfc_s[k] * thloc[k];
                uint32_t dof = off_tp + (uint32_t)(tq * 8 + ci) * 4u;
#pragma unroll
                for (int r = 0; r < 8; r++) st_async_b32(rb[r] + dof, __float_as_uint(tpv), rb[r] + off_mb + mb8);
            }
        }

        // ---- wait for all 8 CTAs' scatters (doubles as part[] reuse guard) ----
        mbar_wait(lmb0 + mb8, (uint32_t)((n >> 1) & 1));

        // ---- phase 3: tiny epilogue (redundant per CTA, warp0 lanes) ----
        if (t < 10) {
            float o = fcbs[t];
#pragma unroll
            for (int c = 0; c < 8; c++) o += pbuf[hq][c][t];
            buf_s[n & 7][t] = o;
            prev_out_s[t + 1] = o;
            if (ci == 0) out[n * 11 + 1 + t] = o;
        }
        if (t == 10) {
            float tv = prevT_s;
            if (start) {
                tv = tfcb_s;
#pragma unroll
                for (int c = 0; c < 8; c++) tv += tpbuf[tq][c];
                prevT_s = tv;
            }
            prev_out_s[0] = tv;
            if (ci == 0) out[n * 11] = tv;
        }
    }
}

// ---------------- host launcher ----------------
extern "C" void kernel_launch(void* const* d_in, const int* in_sizes, int n_in,
                              void* d_out, int out_size)
{
    const float* note     = (const float*)d_in[0];
    const float* beat     = (const float*)d_in[1];
    const float* meas     = (const float*)d_in[2];
    const float* perf     = (const float*)d_in[3];
    const float* res      = (const float*)d_in[4];
    const float* sveW     = (const float*)d_in[5];
    const float* sveb     = (const float*)d_in[6];
    const float* psmWih   = (const float*)d_in[7];
    const float* psmWhh   = (const float*)d_in[8];
    const float* psmb     = (const float*)d_in[9];
    const float* mpfW     = (const float*)d_in[10];
    const float* mpfb     = (const float*)d_in[11];
    const float* attW     = (const float*)d_in[12];
    const float* attb     = (const float*)d_in[13];
    const float* attc     = (const float*)d_in[14];
    const float* tempoWih = (const float*)d_in[15];
    const float* tempoWhh = (const float*)d_in[16];
    const float* tempob   = (const float*)d_in[17];
    const float* tfcW     = (const float*)d_in[18];
    const float* tfcb     = (const float*)d_in[19];
    const float* outWih   = (const float*)d_in[20];
    const float* outWhh   = (const float*)d_in[21];
    const float* outb     = (const float*)d_in[22];
    const float* fcW      = (const float*)d_in[23];
    const float* fcb      = (const float*)d_in[24];

    float *Ppsm, *Hseq, *mps, *POn, *POb, *POm, *PTb, *PTm;
    cudaGetSymbolAddress((void**)&Ppsm, g_Ppsm);
    cudaGetSymbolAddress((void**)&Hseq, g_Hseq);
    cudaGetSymbolAddress((void**)&mps,  g_mps);
    cudaGetSymbolAddress((void**)&POn,  g_POn);
    cudaGetSymbolAddress((void**)&POb,  g_POb);
    cudaGetSymbolAddress((void**)&POm,  g_POm);
    cudaGetSymbolAddress((void**)&PTb,  g_PTb);
    cudaGetSymbolAddress((void**)&PTm,  g_PTm);

    static int smem_set = 0;
    if (!smem_set) {
        cudaFuncSetAttribute(k_seq, cudaFuncAttributeMaxDynamicSharedMemorySize, 131072);
        smem_set = 1;
    }

    k_style<<<1, 128>>>(perf, sveW, sveb);
    k_v0<<<1, 512>>>(psmWih, psmb);
    k_pack_whh<<<1024, 256>>>(outWhh, tempoWhh);
    k_pack_wseq<<<44, 256>>>(outWih, tempoWih);
    k_pack_psm<<<256, 256>>>(psmWhh);

    // psm input projection + psm LSTM + mps
    k_gemm<<<dim3(8, 4), 256>>>(meas, 256, psmWih, 384, 128, Ppsm, 256, 512, 256, nullptr, 0);
    k_psm_seq<<<1, 512>>>();
    k_gemm<<<dim3(2, 4), 256>>>(Hseq, 128, mpfW, 128, 0, mps, 256, 128, 128, mpfb, 0);

    // out-LSTM input projections
    k_gemm<<<dim3(16, 128), 256>>>(note, 512, outWih, 1419, 0,    POn, NN, 1024, 512, nullptr, 0);
    k_gemm<<<dim3(16, 16),  256>>>(beat, 512, outWih, 1419, 512,  POb, NB, 1024, 512, nullptr, 0);
    k_gemm<<<dim3(16, 4),   256>>>(meas, 256, outWih, 1419, 1024, POm, NM, 1024, 256, outb,    0);
    k_gemm<<<dim3(16, 4),   256>>>(mps,  128, outWih, 1419, 1291, POm, NM, 1024, 128, nullptr, 1);

    // tempo-LSTM input projections
    k_gemm<<<dim3(16, 16), 256>>>(beat, 512, tempoWih, 915, 0,   PTb, NB, 1024, 512, tempob,  0);
    k_gemm<<<dim3(16, 16), 256>>>(res,  8,   tempoWih, 915, 769, PTb, NB, 1024, 8,   nullptr, 1);
    k_gemm<<<dim3(16, 4),  256>>>(meas, 256, tempoWih, 915, 512, PTm, NM, 1024, 256, nullptr, 0);
    k_gemm<<<dim3(16, 4),  256>>>(mps,  128, tempoWih, 915, 787, PTm, NM, 1024, 128, nullptr, 1);

    // pre-combine gate inputs
    k_combine_O<<<NN * 4, 256>>>();
    k_combine_T<<<NB * 4, 256>>>();

    // sequential decoder
    k_seq<<<8, 256, 131072>>>(fcW, fcb, tfcW, tfcb, attW, attb, attc, (float*)d_out);
}

// round 5
// speedup vs baseline: 1.1421x; 1.0559x over previous
#include <cuda_runtime.h>
#include <cuda_bf16.h>
#include <math.h>
#include <stdint.h>

#define NN 8192
#define NB 1024
#define NM 256

// ---------------- device scratch (static, no allocation) ----------------
__device__ float g_z[128];
__device__ float g_v0[512];
__device__ float g_Ppsm[NM * 512];
__device__ float g_psmWhh[512 * 128];     // packed [j][r]
__device__ float g_Hseq[NM * 128];
__device__ float g_mps[NM * 128];
__device__ float g_POn[NN * 1024];
__device__ float g_POb[NB * 1024];
__device__ float g_POm[NM * 1024];
__device__ float g_PTb[NB * 1024];
__device__ float g_PTm[NM * 1024];
__device__ float g_preO[NN * 1024];        // [n][c][u][g] gate-interleaved
__device__ float g_preT[NB * 1024];        // [b][c][u][g]
__device__ __align__(16) float g_WhhO[8 * 64 * 128 * 4]; // [c][j4][rl][jj]
__device__ __align__(16) float g_WhhT[8 * 64 * 128 * 4];
__device__ float g_WseqO[8 * 128 * 11];    // [c*128+rl][k]
__device__ float g_WseqT[8 * 128 * 11];

__device__ __forceinline__ float sigm(float x) { return 1.0f / (1.0f + __expf(-x)); }
__device__ __forceinline__ float tanh_fast(float x) { return 2.0f / (1.0f + __expf(-2.0f * x)) - 1.0f; }

__device__ __forceinline__ uint32_t mapa_sh(uint32_t local_addr, uint32_t rank) {
    uint32_t remote;
    asm volatile("mapa.shared::cluster.u32 %0, %1, %2;" : "=r"(remote) : "r"(local_addr), "r"(rank));
    return remote;
}
__device__ __forceinline__ void cluster_sync_all() {
    asm volatile("barrier.cluster.arrive.aligned;" ::: "memory");
    asm volatile("barrier.cluster.wait.aligned;" ::: "memory");
}
__device__ __forceinline__ void st_async_b64(uint32_t raddr, uint64_t v, uint32_t rmbar) {
    asm volatile("st.async.weak.shared::cluster.mbarrier::complete_tx::bytes.b64 [%0], %1, [%2];"
                 :: "r"(raddr), "l"(v), "r"(rmbar) : "memory");
}
__device__ __forceinline__ void st_async_b32(uint32_t raddr, uint32_t v, uint32_t rmbar) {
    asm volatile("st.async.weak.shared::cluster.mbarrier::complete_tx::bytes.b32 [%0], %1, [%2];"
                 :: "r"(raddr), "r"(v), "r"(rmbar) : "memory");
}
__device__ __forceinline__ void mbar_init(uint32_t mb, uint32_t cnt) {
    asm volatile("mbarrier.init.shared.b64 [%0], %1;" :: "r"(mb), "r"(cnt) : "memory");
}
__device__ __forceinline__ void mbar_expect(uint32_t mb, uint32_t tx) {
    asm volatile("mbarrier.arrive.expect_tx.shared.b64 _, [%0], %1;" :: "r"(mb), "r"(tx) : "memory");
}
__device__ __forceinline__ void mbar_wait(uint32_t mb, uint32_t ph) {
    asm volatile(
        "{\n\t.reg .pred P;\n"
        "LW_%=:\n\t"
        "mbarrier.try_wait.parity.acquire.cluster.shared::cta.b64 P, [%0], %1, 0x989680;\n\t"
        "@P bra LD_%=;\n\t"
        "bra LW_%=;\n"
        "LD_%=:\n\t}"
        :: "r"(mb), "r"(ph) : "memory");
}
__device__ __forceinline__ uint64_t pk2(float x, float y) {
    uint64_t r; asm("mov.b64 %0, {%1, %2};" : "=l"(r) : "f"(x), "f"(y)); return r;
}
__device__ __forceinline__ void ffma2(uint64_t& acc, uint64_t a, uint64_t b) {
    asm("fma.rn.f32x2 %0, %1, %2, %0;" : "+l"(acc) : "l"(a), "l"(b));
}
__device__ __forceinline__ float upk_sum(uint64_t a) {
    float lo, hi; asm("mov.b64 {%0, %1}, %2;" : "=f"(lo), "=f"(hi) : "l"(a)); return lo + hi;
}
__device__ __forceinline__ uint64_t d2u(double d) { return __double_as_longlong(d); }

// ---------------- generic tiled GEMM: C[M][N] (+)= X[M][K] @ W[:, wofs:wofs+K]^T (+bias) ----
__global__ void k_gemm(const float* __restrict__ X, int ldx,
                       const float* __restrict__ W, int ldw, int wofs,
                       float* __restrict__ C, int M, int N, int K,
                       const float* __restrict__ bias, int accum)
{
    __shared__ float Xs[16][65];
    __shared__ float Ws[16][65];
    int tid = threadIdx.x;
    int tx = tid & 15, ty = tid >> 4;
    int n0 = blockIdx.x * 64, m0 = blockIdx.y * 64;
    float acc[4][4];
#pragma unroll
    for (int i = 0; i < 4; i++)
#pragma unroll
        for (int j = 0; j < 4; j++) acc[i][j] = 0.f;

    for (int k0 = 0; k0 < K; k0 += 16) {
        for (int i = tid; i < 1024; i += 256) {
            int mm = i >> 4, kk = i & 15;
            int k = k0 + kk;
            Xs[kk][mm] = (k < K) ? X[(size_t)(m0 + mm) * ldx + k] : 0.f;
            Ws[kk][mm] = (k < K) ? W[(size_t)(n0 + mm) * ldw + wofs + k] : 0.f;
        }
        __syncthreads();
#pragma unroll
        for (int kk = 0; kk < 16; kk++) {
            float a[4], b[4];
#pragma unroll
            for (int i = 0; i < 4; i++) a[i] = Xs[kk][ty * 4 + i];
#pragma unroll
            for (int j = 0; j < 4; j++) b[j] = Ws[kk][tx * 4 + j];
#pragma unroll
            for (int i = 0; i < 4; i++)
#pragma unroll
                for (int j = 0; j < 4; j++) acc[i][j] += a[i] * b[j];
        }
        __syncthreads();
    }
#pragma unroll
    for (int i = 0; i < 4; i++) {
        int m = m0 + ty * 4 + i;
#pragma unroll
        for (int j = 0; j < 4; j++) {
            int n = n0 + tx * 4 + j;
            float v = acc[i][j];
            if (bias) v += bias[n];
            size_t o = (size_t)m * N + n;
            if (accum) v += C[o];
            C[o] = v;
        }
    }
}

// ---------------- small prep kernels ----------------
__global__ void k_style(const float* __restrict__ perf, const float* __restrict__ sveW,
                        const float* __restrict__ sveb)
{
    int r = threadIdx.x; // 128
    float s = sveb[r];
    for (int k = 0; k < 64; k++) s += sveW[r * 64 + k] * perf[k];
    g_z[r] = fmaxf(s, 0.f);
}

__global__ void k_v0(const float* __restrict__ psmWih, const float* __restrict__ psmb)
{
    int r = threadIdx.x; // 512
    float s = psmb[r];
    for (int k = 0; k < 128; k++) s += psmWih[r * 384 + k] * g_z[k];
    g_v0[r] = s;
}

__global__ void k_pack_psm(const float* __restrict__ psmWhh)
{
    int idx = blockIdx.x * 256 + threadIdx.x; // 65536
    int r = idx & 511, j = idx >> 9;
    g_psmWhh[idx] = psmWhh[r * 128 + j];
}

__global__ void k_pack_whh(const float* __restrict__ whhO, const float* __restrict__ whhT)
{
    int idx = blockIdx.x * 256 + threadIdx.x; // 262144
    int jj = idx & 3, rl = (idx >> 2) & 127, j4 = (idx >> 9) & 63, c = idx >> 15;
    int grow = (rl >> 5) * 256 + c * 32 + (rl & 31);
    int col = j4 * 4 + jj;
    g_WhhO[idx] = whhO[grow * 256 + col];
    g_WhhT[idx] = whhT[grow * 256 + col];
}

__global__ void k_pack_wseq(const float* __restrict__ outWih, const float* __restrict__ tempoWih)
{
    int idx = blockIdx.x * 256 + threadIdx.x;
    if (idx >= 8 * 128 * 11) return;
    int k = idx % 11;
    int rc = idx / 11;              // c*128 + rl
    int rl = rc & 127, c = rc >> 7;
    int grow = (rl >> 5) * 256 + c * 32 + (rl & 31);
    g_WseqO[idx] = outWih[(size_t)grow * 1419 + 1280 + k];
    int col = (k == 0) ? 768 : (776 + k);
    g_WseqT[idx] = tempoWih[(size_t)grow * 915 + col];
}

// combine the three out-LSTM input projections into gate-interleaved preO
__global__ void k_combine_O()
{
    int idx = blockIdx.x * 256 + threadIdx.x;  // NN*1024
    int n = idx >> 10, grow = idx & 1023;
    int b = n >> 3, m = n >> 5;
    float v = g_POn[idx] + g_POb[b * 1024 + grow] + g_POm[m * 1024 + grow];
    int g = grow >> 8, c = (grow >> 5) & 7, uu = grow & 31;
    g_preO[(n << 10) + c * 128 + uu * 4 + g] = v;
}

__global__ void k_combine_T()
{
    int idx = blockIdx.x * 256 + threadIdx.x;  // NB*1024
    int bq = idx >> 10, grow = idx & 1023;
    int m = bq >> 2;
    float v = g_PTb[idx] + g_PTm[m * 1024 + grow];
    int g = grow >> 8, c = (grow >> 5) & 7, uu = grow & 31;
    g_preT[(bq << 10) + c * 128 + uu * 4 + g] = v;
}

// ---------------- psm LSTM over 256 measures (one CTA, 512 threads) ----------------
__global__ void __launch_bounds__(512, 1) k_psm_seq()
{
    __shared__ float h[128], cst[128];
    __shared__ float part[4][512];
    __shared__ float gate[512];
    int t = threadIdx.x;
    int a = t & 127, jg = t >> 7;
    if (t < 128) { h[t] = 0.f; cst[t] = 0.f; }
    __syncthreads();
    for (int m = 0; m < NM; m++) {
        float a0 = 0, a1 = 0, a2 = 0, a3 = 0;
#pragma unroll 4
        for (int jj = 0; jj < 32; jj++) {
            int j = jg * 32 + jj;
            float4 w = *(const float4*)(g_psmWhh + j * 512 + 4 * a);
            float hv = h[j];
            a0 += w.x * hv; a1 += w.y * hv; a2 += w.z * hv; a3 += w.w * hv;
        }
        part[jg][4 * a + 0] = a0; part[jg][4 * a + 1] = a1;
        part[jg][4 * a + 2] = a2; part[jg][4 * a + 3] = a3;
        __syncthreads();
        {
            float s = g_Ppsm[m * 512 + t] + g_v0[t];
#pragma unroll
            for (int gg = 0; gg < 4; gg++) s += part[gg][t];
            gate[t] = s;
        }
        __syncthreads();
        if (t < 128) {
            float cn = sigm(gate[128 + t]) * cst[t] + sigm(gate[t]) * tanhf(gate[256 + t]);
            cst[t] = cn;
            float hn = sigm(gate[384 + t]) * tanhf(cn);
            h[t] = hn;
            g_Hseq[m * 128 + t] = hn;
        }
        __syncthreads();
    }
}

// ---------------- sequential decoder: 8-CTA cluster, 256 thr/CTA, mbarrier sync ----------------
__global__ void __cluster_dims__(8, 1, 1) __launch_bounds__(256, 1)
k_seq(const float* __restrict__ fcW, const float* __restrict__ fcb,
      const float* __restrict__ tfcW, const float* __restrict__ tfcb,
      const float* __restrict__ attW, const float* __restrict__ attb,
      const float* __restrict__ attc, float* __restrict__ out)
{
    extern __shared__ double2 WhhT_sm[];              // 64*128 double2 per CTA = 128 KB

    __shared__ __align__(16) float hbuf[2][256];
    __shared__ __align__(16) float thbuf[2][256];
    __shared__ __align__(16) float part[2][128];
    __shared__ __align__(16) float partT[2][128];
    __shared__ float WsO[128][11], WsT[128][11];
    __shared__ float fcw_s[10][32];
    __shared__ float tfc_s[32];
    __shared__ float attWs[10][10], attbs[10], attcs[10], fcbs[10];
    __shared__ float buf_s[8][10];
    __shared__ float prev_out_s[11];
    __shared__ float result_s[10];
    __shared__ float wsoft[8];
    __shared__ float hloc[32], thloc[32];
    __shared__ __align__(8) float pbuf[2][8][12];     // 12-padded rows for b64 alignment
    __shared__ float tpbuf[2][8];
    __shared__ float prevT_s, tfcb_s;
    __shared__ __align__(8) uint64_t mbar_s[2];

    const int t = threadIdx.x;
    uint32_t crank;
    asm("mov.u32 %0, %%cluster_ctarank;" : "=r"(crank));
    const int rl = t & 127, s = t >> 7;       // s in {0,1}: k-half
    const int u = t & 31;
    const int wid = t >> 5;
    const int ci = (int)crank;

    // ---- register-resident out-LSTM Whh slice: 128 weights/thread as 32 double2 ----
    double2 wreg[32];
    {
        const double2* src = (const double2*)g_WhhO;
#pragma unroll
        for (int ii = 0; ii < 32; ii++)
            wreg[ii] = src[(size_t)(ci * 64 + s * 32 + ii) * 128 + rl];
    }
    // ---- tempo Whh slice into dynamic smem (same layout) ----
    {
        const double2* src = (const double2*)g_WhhT;
        for (int i = t; i < 8192; i += 256)
            WhhT_sm[i] = src[(size_t)ci * 8192 + i];
    }
    if (t < 128) {
#pragma unroll
        for (int k = 0; k < 11; k++) {
            WsO[t][k] = g_WseqO[(ci * 128 + t) * 11 + k];
            WsT[t][k] = g_WseqT[(ci * 128 + t) * 11 + k];
        }
    }
    for (int i = t; i < 320; i += 256) fcw_s[i >> 5][i & 31] = fcW[(i >> 5) * 256 + ci * 32 + (i & 31)];
    if (t < 32)  tfc_s[t] = tfcW[ci * 32 + t];
    if (t < 256) { hbuf[0][t] = 0.f; hbuf[1][t] = 0.f; thbuf[0][t] = 0.f; thbuf[1][t] = 0.f; }
    if (t < 100) attWs[t / 10][t % 10] = attW[t];
    if (t < 10)  { attbs[t] = attb[t]; attcs[t] = attc[t]; fcbs[t] = fcb[t]; result_s[t] = 0.f; }
    if (t < 11)  prev_out_s[t] = 0.f;
    if (t < 80)  buf_s[t / 10][t % 10] = 0.f;
    for (int i = t; i < 192; i += 256) pbuf[i / 96][(i / 12) & 7][i % 12] = 0.f;
    if (t < 16)  tpbuf[t >> 3][t & 7] = 0.f;
    if (t == 0)  { tfcb_s = tfcb[0]; prevT_s = 0.f; }

    const uint32_t sb = (uint32_t)__cvta_generic_to_shared(&hbuf[0][0]);
    const uint32_t off_th = (uint32_t)__cvta_generic_to_shared(&thbuf[0][0]) - sb;
    const uint32_t off_pb = (uint32_t)__cvta_generic_to_shared(&pbuf[0][0][0]) - sb;
    const uint32_t off_tp = (uint32_t)__cvta_generic_to_shared(&tpbuf[0][0]) - sb;
    const uint32_t off_mb = (uint32_t)__cvta_generic_to_shared(&mbar_s[0]) - sb;
    const uint32_t lmb0 = sb + off_mb;

    if (t == 0) { mbar_init(lmb0, 1); mbar_init(lmb0 + 8, 1); }
    __syncthreads();
    cluster_sync_all();   // one-time: mbar init + smem staging visible cluster-wide

    uint32_t rb[8];
#pragma unroll
    for (int r = 0; r < 8; r++) rb[r] = mapa_sh(sb, (uint32_t)r);

    float cst = 0.f;   // out-LSTM cell (warp0 lanes)
    float tcst = 0.f;  // tempo cell   (warp1 lanes)
    float4 pvn = make_float4(0.f, 0.f, 0.f, 0.f);
    float4 pvTn = pvn;
    if (wid == 0) pvn  = *(const float4*)(g_preO + ci * 128 + 4 * u);
    if (wid == 1) pvTn = *(const float4*)(g_preT + ci * 128 + 4 * u);

    const uint32_t EXP_NS = 8 * 32 * 4 + 8 * 10 * 4;              // 1344
    const uint32_t EXP_S  = EXP_NS + 8 * 32 * 4 + 8 * 4;          // 2400

    for (int n = 0; n < NN; n++) {
        const int b = n >> 3;
        const bool start = (n & 7) == 0;
        const int hq = (n + 1) & 1;       // write parity this step
        const int hp = n & 1;             // h read parity
        const int tp = (b & 1);
        const int tq = (b + 1) & 1;
        const uint32_t mb8 = (uint32_t)(n & 1) * 8u;

        // ---- arm local barrier for this step ----
        if (t == 0) mbar_expect(lmb0 + mb8, start ? EXP_S : EXP_NS);

        // ---- phase 1: matvec partials (+ prefetch next-step inputs) ----
        float4 pvc = make_float4(0.f, 0.f, 0.f, 0.f), pvTc = pvc;
        if (wid == 0) {
            pvc = pvn;
            int nn = (n + 1 < NN) ? n + 1 : n;
            pvn = *(const float4*)(g_preO + nn * 1024 + ci * 128 + 4 * u);
        }
        if (wid == 1 && start) {
            pvTc = pvTn;
            int bb = (b + 1 < NB) ? b + 1 : b;
            pvTn = *(const float4*)(g_preT + bb * 1024 + ci * 128 + 4 * u);
        }
        {
            const double2* hb2 = (const double2*)hbuf[hp];
            uint64_t A0 = 0ull, A1 = 0ull, A2 = 0ull, A3 = 0ull;
#pragma unroll
            for (int ii = 0; ii < 32; ii += 2) {
                double2 h0 = hb2[s * 32 + ii];
                double2 h1 = hb2[s * 32 + ii + 1];
                ffma2(A0, d2u(wreg[ii].x), d2u(h0.x));
                ffma2(A1, d2u(wreg[ii].y), d2u(h0.y));
                ffma2(A2, d2u(wreg[ii + 1].x), d2u(h1.x));
                ffma2(A3, d2u(wreg[ii + 1].y), d2u(h1.y));
            }
            part[s][rl] = upk_sum(A0) + upk_sum(A1) + upk_sum(A2) + upk_sum(A3);
        }
        if (start) {
            const double2* hb2 = (const double2*)thbuf[tp];
            uint64_t A0 = 0ull, A1 = 0ull;
#pragma unroll 8
            for (int ii = 0; ii < 32; ii++) {
                double2 wv = WhhT_sm[(s * 32 + ii) * 128 + rl];
                double2 hv = hb2[s * 32 + ii];
                ffma2(A0, d2u(wv.x), d2u(hv.x));
                ffma2(A1, d2u(wv.y), d2u(hv.y));
            }
            partT[s][rl] = upk_sum(A0) + upk_sum(A1);
        }
        __syncthreads();

        // ---- phase 2 ----
        if (wid == 0) {
            float gi = pvc.x + part[0][u]      + part[1][u];
            float gf = pvc.y + part[0][u + 32] + part[1][u + 32];
            float gG = pvc.z + part[0][u + 64] + part[1][u + 64];
            float go = pvc.w + part[0][u + 96] + part[1][u + 96];
#pragma unroll
            for (int k = 0; k < 11; k++) {
                float pk = prev_out_s[k];
                gi += WsO[u][k] * pk;
                gf += WsO[u + 32][k] * pk;
                gG += WsO[u + 64][k] * pk;
                go += WsO[u + 96][k] * pk;
            }
            float cn = sigm(gf) * cst + sigm(gi) * tanh_fast(gG);
            cst = cn;
            float hn = sigm(go) * tanh_fast(cn);
            hloc[u] = hn;
            __syncwarp();
            float p = 0.f;
            if (u < 10) {
#pragma unroll
                for (int k = 0; k < 32; k++) p += fcw_s[u][k] * hloc[k];
            }
            float hnx = __shfl_down_sync(0xffffffffu, hn, 1);
            if (!(u & 1)) {
                uint64_t hv2 = pk2(hn, hnx);
                uint32_t dof = (uint32_t)(hq * 256 + ci * 32 + u) * 4u;
#pragma unroll
                for (int r = 0; r < 8; r++) st_async_b64(rb[r] + dof, hv2, rb[r] + off_mb + mb8);
            }
            float pa = __shfl_sync(0xffffffffu, p, 2 * u);
            float pb_ = __shfl_sync(0xffffffffu, p, 2 * u + 1);
            if (u < 5) {
                uint64_t pv2 = pk2(pa, pb_);
                uint32_t dof = off_pb + (uint32_t)(hq * 96 + ci * 12 + 2 * u) * 4u;
#pragma unroll
                for (int r = 0; r < 8; r++) st_async_b64(rb[r] + dof, pv2, rb[r] + off_mb + mb8);
            }
        } else if (wid == 1 && start) {
            // attention over previous beat
            if (b > 0) {
                float sc = -1e30f;
                if (u < 8) {
                    sc = 0.f;
#pragma unroll
                    for (int j = 0; j < 10; j++) {
                        float a = attbs[j];
#pragma unroll
                        for (int k = 0; k < 10; k++) a += attWs[j][k] * buf_s[u][k];
                        sc += tanh_fast(a) * attcs[j];
                    }
                }
                float mx = sc;
#pragma unroll
                for (int off = 16; off; off >>= 1) mx = fmaxf(mx, __shfl_xor_sync(0xffffffffu, mx, off));
                float e = __expf(sc - mx);
                float sm = e;
#pragma unroll
                for (int off = 16; off; off >>= 1) sm += __shfl_xor_sync(0xffffffffu, sm, off);
                if (u < 8) wsoft[u] = e / sm;
                __syncwarp();
                if (u < 10) {
                    float r = 0.f;
#pragma unroll
                    for (int p = 0; p < 8; p++) r += wsoft[p] * buf_s[p][u];
                    result_s[u] = r;
                }
            } else {
                if (u < 10) result_s[u] = 0.f;
            }
            __syncwarp();
            float gi = pvTc.x + partT[0][u]      + partT[1][u];
            float gf = pvTc.y + partT[0][u + 32] + partT[1][u + 32];
            float gG = pvTc.z + partT[0][u + 64] + partT[1][u + 64];
            float go = pvTc.w + partT[0][u + 96] + partT[1][u + 96];
            {
                float p0 = prevT_s;
                gi += WsT[u][0] * p0;
                gf += WsT[u + 32][0] * p0;
                gG += WsT[u + 64][0] * p0;
                go += WsT[u + 96][0] * p0;
            }
#pragma unroll
            for (int k = 0; k < 10; k++) {
                float rk = result_s[k];
                gi += WsT[u][1 + k] * rk;
                gf += WsT[u + 32][1 + k] * rk;
                gG += WsT[u + 64][1 + k] * rk;
                go += WsT[u + 96][1 + k] * rk;
            }
            float cn = sigm(gf) * tcst + sigm(gi) * tanh_fast(gG);
            tcst = cn;
            float hn = sigm(go) * tanh_fast(cn);
            thloc[u] = hn;
            __syncwarp();
            float hnx = __shfl_down_sync(0xffffffffu, hn, 1);
            if (!(u & 1)) {
                uint64_t hv2 = pk2(hn, hnx);
                uint32_t dof = off_th + (uint32_t)(tq * 256 + ci * 32 + u) * 4u;
#pragma unroll
                for (int r = 0; r < 8; r++) st_async_b64(rb[r] + dof, hv2, rb[r] + off_mb + mb8);
            }
            if (u == 0) {
                float tpv = 0.f;
#pragma unroll
                for (int k = 0; k < 32; k++) tpv += tfc_s[k] * thloc[k];
                uint32_t dof = off_tp + (uint32_t)(tq * 8 + ci) * 4u;
#pragma unroll
                for (int r = 0; r < 8; r++) st_async_b32(rb[r] + dof, __float_as_uint(tpv), rb[r] + off_mb + mb8);
            }
        }

        // ---- wait for all 8 CTAs' scatters (doubles as part[] reuse guard) ----
        mbar_wait(lmb0 + mb8, (uint32_t)((n >> 1) & 1));

        // ---- phase 3: tiny epilogue (redundant per CTA, warp0 lanes) ----
        if (t < 10) {
            float o = fcbs[t];
#pragma unroll
            for (int c = 0; c < 8; c++) o += pbuf[hq][c][t];
            buf_s[n & 7][t] = o;
            prev_out_s[t + 1] = o;
            if (ci == 0) out[n * 11 + 1 + t] = o;
        }
        if (t == 10) {
            float tv = prevT_s;
            if (start) {
                tv = tfcb_s;
#pragma unroll
                for (int c = 0; c < 8; c++) tv += tpbuf[tq][c];
                prevT_s = tv;
            }
            prev_out_s[0] = tv;
            if (ci == 0) out[n * 11] = tv;
        }
    }
}

// ---------------- host launcher ----------------
extern "C" void kernel_launch(void* const* d_in, const int* in_sizes, int n_in,
                              void* d_out, int out_size)
{
    const float* note     = (const float*)d_in[0];
    const float* beat     = (const float*)d_in[1];
    const float* meas     = (const float*)d_in[2];
    const float* perf     = (const float*)d_in[3];
    const float* res      = (const float*)d_in[4];
    const float* sveW     = (const float*)d_in[5];
    const float* sveb     = (const float*)d_in[6];
    const float* psmWih   = (const float*)d_in[7];
    const float* psmWhh   = (const float*)d_in[8];
    const float* psmb     = (const float*)d_in[9];
    const float* mpfW     = (const float*)d_in[10];
    const float* mpfb     = (const float*)d_in[11];
    const float* attW     = (const float*)d_in[12];
    const float* attb     = (const float*)d_in[13];
    const float* attc     = (const float*)d_in[14];
    const float* tempoWih = (const float*)d_in[15];
    const float* tempoWhh = (const float*)d_in[16];
    const float* tempob   = (const float*)d_in[17];
    const float* tfcW     = (const float*)d_in[18];
    const float* tfcb     = (const float*)d_in[19];
    const float* outWih   = (const float*)d_in[20];
    const float* outWhh   = (const float*)d_in[21];
    const float* outb     = (const float*)d_in[22];
    const float* fcW      = (const float*)d_in[23];
    const float* fcb      = (const float*)d_in[24];

    float *Ppsm, *Hseq, *mps, *POn, *POb, *POm, *PTb, *PTm;
    cudaGetSymbolAddress((void**)&Ppsm, g_Ppsm);
    cudaGetSymbolAddress((void**)&Hseq, g_Hseq);
    cudaGetSymbolAddress((void**)&mps,  g_mps);
    cudaGetSymbolAddress((void**)&POn,  g_POn);
    cudaGetSymbolAddress((void**)&POb,  g_POb);
    cudaGetSymbolAddress((void**)&POm,  g_POm);
    cudaGetSymbolAddress((void**)&PTb,  g_PTb);
    cudaGetSymbolAddress((void**)&PTm,  g_PTm);

    static int smem_set = 0;
    if (!smem_set) {
        cudaFuncSetAttribute(k_seq, cudaFuncAttributeMaxDynamicSharedMemorySize, 131072);
        smem_set = 1;
    }

    k_style<<<1, 128>>>(perf, sveW, sveb);
    k_v0<<<1, 512>>>(psmWih, psmb);
    k_pack_whh<<<1024, 256>>>(outWhh, tempoWhh);
    k_pack_wseq<<<44, 256>>>(outWih, tempoWih);
    k_pack_psm<<<256, 256>>>(psmWhh);

    // psm input projection + psm LSTM + mps
    k_gemm<<<dim3(8, 4), 256>>>(meas, 256, psmWih, 384, 128, Ppsm, 256, 512, 256, nullptr, 0);
    k_psm_seq<<<1, 512>>>();
    k_gemm<<<dim3(2, 4), 256>>>(Hseq, 128, mpfW, 128, 0, mps, 256, 128, 128, mpfb, 0);

    // out-LSTM input projections
    k_gemm<<<dim3(16, 128), 256>>>(note, 512, outWih, 1419, 0,    POn, NN, 1024, 512, nullptr, 0);
    k_gemm<<<dim3(16, 16),  256>>>(beat, 512, outWih, 1419, 512,  POb, NB, 1024, 512, nullptr, 0);
    k_gemm<<<dim3(16, 4),   256>>>(meas, 256, outWih, 1419, 1024, POm, NM, 1024, 256, outb,    0);
    k_gemm<<<dim3(16, 4),   256>>>(mps,  128, outWih, 1419, 1291, POm, NM, 1024, 128, nullptr, 1);

    // tempo-LSTM input projections
    k_gemm<<<dim3(16, 16), 256>>>(beat, 512, tempoWih, 915, 0,   PTb, NB, 1024, 512, tempob,  0);
    k_gemm<<<dim3(16, 16), 256>>>(res,  8,   tempoWih, 915, 769, PTb, NB, 1024, 8,   nullptr, 1);
    k_gemm<<<dim3(16, 4),  256>>>(meas, 256, tempoWih, 915, 512, PTm, NM, 1024, 256, nullptr, 0);
    k_gemm<<<dim3(16, 4),  256>>>(mps,  128, tempoWih, 915, 787, PTm, NM, 1024, 128, nullptr, 1);

    // pre-combine gate inputs
    k_combine_O<<<NN * 4, 256>>>();
    k_combine_T<<<NB * 4, 256>>>();

    // sequential decoder
    k_seq<<<8, 256, 131072>>>(fcW, fcb, tfcW, tfcb, attW, attb, attc, (float*)d_out);
}

// round 6
// speedup vs baseline: 1.2258x; 1.0733x over previous
#include <cuda_runtime.h>
#include <math.h>
#include <stdint.h>
typedef unsigned long long u64;

#define NN 8192
#define NB 1024
#define NM 256

__device__ float g_z[128];
__device__ float g_v0[512];
__device__ float g_Ppsm[NM * 512];
__device__ float g_psmWhh[512 * 128];
__device__ float g_Hseq[NM * 128];
__device__ float g_mps[NM * 128];
__device__ float g_POn[NN * 1024];
__device__ float g_POb[NB * 1024];
__device__ float g_POm[NM * 1024];
__device__ float g_PTb[NB * 1024];
__device__ float g_PTm[NM * 1024];
__device__ float g_preO[NN * 1024];   // [n][ci][u][gate]
__device__ float g_preT[NB * 1024];   // [b][ci][u][gate]
__device__ u64 g_WO2[131072];         // [ci][w][kp][g][u] k-pairs
__device__ u64 g_WT2[131072];
__device__ float g_WseqO[8 * 128 * 11];
__device__ float g_WseqT[8 * 128 * 11];

__device__ __forceinline__ float sigm(float x) { return 1.0f / (1.0f + __expf(-x)); }
__device__ __forceinline__ float tanh_fast(float x) { return 2.0f / (1.0f + __expf(-2.0f * x)) - 1.0f; }
__device__ __forceinline__ uint32_t mapa_sh(uint32_t a, uint32_t r) {
    uint32_t q; asm volatile("mapa.shared::cluster.u32 %0, %1, %2;" : "=r"(q) : "r"(a), "r"(r));
    return q;
}
__device__ __forceinline__ void cluster_sync_all() {
    asm volatile("barrier.cluster.arrive.aligned;" ::: "memory");
    asm volatile("barrier.cluster.wait.aligned;" ::: "memory");
}
__device__ __forceinline__ void mbar_init(uint32_t mb, uint32_t c) {
    asm volatile("mbarrier.init.shared.b64 [%0], %1;" :: "r"(mb), "r"(c) : "memory");
}
__device__ __forceinline__ void mbar_expect(uint32_t mb, uint32_t tx) {
    asm volatile("mbarrier.arrive.expect_tx.shared.b64 _, [%0], %1;" :: "r"(mb), "r"(tx) : "memory");
}
__device__ __forceinline__ void mbar_wait(uint32_t mb, uint32_t ph) {
    asm volatile(
        "{\n\t.reg .pred P;\n"
        "LW_%=:\n\t"
        "mbarrier.try_wait.parity.acquire.cluster.shared::cta.b64 P, [%0], %1, 0x989680;\n\t"
        "@P bra LD_%=;\n\t"
        "bra LW_%=;\n"
        "LD_%=:\n\t}"
        :: "r"(mb), "r"(ph) : "memory");
}
__device__ __forceinline__ void bulk_cluster(uint32_t dst, uint32_t src, uint32_t bytes, uint32_t mb) {
    asm volatile("cp.async.bulk.shared::cluster.shared::cta.mbarrier::complete_tx::bytes [%0], [%1], %2, [%3];"
                 :: "r"(dst), "r"(src), "r"(bytes), "r"(mb) : "memory");
}
__device__ __forceinline__ void bulk_commit() { asm volatile("cp.async.bulk.commit_group;" ::: "memory"); }
__device__ __forceinline__ void bulk_wait_read() { asm volatile("cp.async.bulk.wait_group.read 0;" ::: "memory"); }
__device__ __forceinline__ void ffma2(u64& acc, u64 a, u64 b) {
    asm("fma.rn.f32x2 %0, %1, %2, %0;" : "+l"(acc) : "l"(a), "l"(b));
}
__device__ __forceinline__ float upk_sum(u64 a) {
    float lo, hi; asm("mov.b64 {%0, %1}, %2;" : "=f"(lo), "=f"(hi) : "l"(a)); return lo + hi;
}

// ---------------- GEMM: C[M][N] (+)= X[M][K] @ W[:, wofs:wofs+K]^T (+bias) ----
__global__ void k_gemm(const float* __restrict__ X, int ldx,
                       const float* __restrict__ W, int ldw, int wofs,
                       float* __restrict__ C, int M, int N, int K,
                       const float* __restrict__ bias, int accum)
{
    __shared__ float Xs[16][65];
    __shared__ float Ws[16][65];
    int tid = threadIdx.x;
    int tx = tid & 15, ty = tid >> 4;
    int n0 = blockIdx.x * 64, m0 = blockIdx.y * 64;
    float acc[4][4];
#pragma unroll
    for (int i = 0; i < 4; i++)
#pragma unroll
        for (int j = 0; j < 4; j++) acc[i][j] = 0.f;
    for (int k0 = 0; k0 < K; k0 += 16) {
        for (int i = tid; i < 1024; i += 256) {
            int mm = i >> 4, kk = i & 15;
            int k = k0 + kk;
            Xs[kk][mm] = (k < K) ? X[(size_t)(m0 + mm) * ldx + k] : 0.f;
            Ws[kk][mm] = (k < K) ? W[(size_t)(n0 + mm) * ldw + wofs + k] : 0.f;
        }
        __syncthreads();
#pragma unroll
        for (int kk = 0; kk < 16; kk++) {
            float a[4], b[4];
#pragma unroll
            for (int i = 0; i < 4; i++) a[i] = Xs[kk][ty * 4 + i];
#pragma unroll
            for (int j = 0; j < 4; j++) b[j] = Ws[kk][tx * 4 + j];
#pragma unroll
            for (int i = 0; i < 4; i++)
#pragma unroll
                for (int j = 0; j < 4; j++) acc[i][j] += a[i] * b[j];
        }
        __syncthreads();
    }
#pragma unroll
    for (int i = 0; i < 4; i++) {
        int m = m0 + ty * 4 + i;
#pragma unroll
        for (int j = 0; j < 4; j++) {
            int n = n0 + tx * 4 + j;
            float v = acc[i][j];
            if (bias) v += bias[n];
            size_t o = (size_t)m * N + n;
            if (accum) v += C[o];
            C[o] = v;
        }
    }
}

__global__ void k_style(const float* __restrict__ perf, const float* __restrict__ sveW,
                        const float* __restrict__ sveb)
{
    int r = threadIdx.x;
    float s = sveb[r];
    for (int k = 0; k < 64; k++) s += sveW[r * 64 + k] * perf[k];
    g_z[r] = fmaxf(s, 0.f);
}

__global__ void k_v0(const float* __restrict__ psmWih, const float* __restrict__ psmb)
{
    int r = threadIdx.x;
    float s = psmb[r];
    for (int k = 0; k < 128; k++) s += psmWih[r * 384 + k] * g_z[k];
    g_v0[r] = s;
}

__global__ void k_pack_psm(const float* __restrict__ psmWhh)
{
    int idx = blockIdx.x * 256 + threadIdx.x;
    int r = idx & 511, j = idx >> 9;
    g_psmWhh[idx] = psmWhh[r * 128 + j];
}

__global__ void k_pack_w2(const float* __restrict__ whhO, const float* __restrict__ whhT)
{
    int idx = blockIdx.x * 256 + threadIdx.x;   // 131072
    int u = idx & 31, g = (idx >> 5) & 3, kp = (idx >> 7) & 15, w = (idx >> 11) & 7, ci = idx >> 14;
    int row = g * 256 + ci * 32 + u;
    int k0 = w * 32 + kp * 2;
    g_WO2[idx] = (u64)__float_as_uint(whhO[row * 256 + k0]) |
                 ((u64)__float_as_uint(whhO[row * 256 + k0 + 1]) << 32);
    g_WT2[idx] = (u64)__float_as_uint(whhT[row * 256 + k0]) |
                 ((u64)__float_as_uint(whhT[row * 256 + k0 + 1]) << 32);
}

__global__ void k_pack_wseq(const float* __restrict__ outWih, const float* __restrict__ tempoWih)
{
    int idx = blockIdx.x * 256 + threadIdx.x;
    if (idx >= 8 * 128 * 11) return;
    int k = idx % 11;
    int rc = idx / 11;
    int rl = rc & 127, c = rc >> 7;
    int grow = (rl >> 5) * 256 + c * 32 + (rl & 31);
    g_WseqO[idx] = outWih[(size_t)grow * 1419 + 1280 + k];
    int col = (k == 0) ? 768 : (776 + k);
    g_WseqT[idx] = tempoWih[(size_t)grow * 915 + col];
}

__global__ void k_combine_O()
{
    int idx = blockIdx.x * 256 + threadIdx.x;
    int n = idx >> 10, grow = idx & 1023;
    int b = n >> 3, m = n >> 5;
    float v = g_POn[idx] + g_POb[b * 1024 + grow] + g_POm[m * 1024 + grow];
    int g = grow >> 8, c = (grow >> 5) & 7, uu = grow & 31;
    g_preO[(n << 10) + c * 128 + uu * 4 + g] = v;
}

__global__ void k_combine_T()
{
    int idx = blockIdx.x * 256 + threadIdx.x;
    int bq = idx >> 10, grow = idx & 1023;
    int m = bq >> 2;
    float v = g_PTb[idx] + g_PTm[m * 1024 + grow];
    int g = grow >> 8, c = (grow >> 5) & 7, uu = grow & 31;
    g_preT[(bq << 10) + c * 128 + uu * 4 + g] = v;
}

__global__ void __launch_bounds__(512, 1) k_psm_seq()
{
    __shared__ float h[128], cst[128];
    __shared__ float part[4][512];
    __shared__ float gate[512];
    int t = threadIdx.x;
    int a = t & 127, jg = t >> 7;
    if (t < 128) { h[t] = 0.f; cst[t] = 0.f; }
    __syncthreads();
    for (int m = 0; m < NM; m++) {
        float a0 = 0, a1 = 0, a2 = 0, a3 = 0;
#pragma unroll 4
        for (int jj = 0; jj < 32; jj++) {
            int j = jg * 32 + jj;
            float4 w = *(const float4*)(g_psmWhh + j * 512 + 4 * a);
            float hv = h[j];
            a0 += w.x * hv; a1 += w.y * hv; a2 += w.z * hv; a3 += w.w * hv;
        }
        part[jg][4 * a + 0] = a0; part[jg][4 * a + 1] = a1;
        part[jg][4 * a + 2] = a2; part[jg][4 * a + 3] = a3;
        __syncthreads();
        {
            float s = g_Ppsm[m * 512 + t] + g_v0[t];
#pragma unroll
            for (int gg = 0; gg < 4; gg++) s += part[gg][t];
            gate[t] = s;
        }
        __syncthreads();
        if (t < 128) {
            float cn = sigm(gate[128 + t]) * cst[t] + sigm(gate[t]) * tanhf(gate[256 + t]);
            cst[t] = cn;
            float hn = sigm(gate[384 + t]) * tanhf(cn);
            h[t] = hn;
            g_Hseq[m * 128 + t] = hn;
        }
        __syncthreads();
    }
}

// ---- sequential decoder: 8-CTA cluster, 256 thr, bulk DSMEM exchange ----
// outbox floats: [0:32) h, [32:64) tempo h, [64:74) fc partials, [74] tempo fc partial, [75:80) pad
__global__ void __cluster_dims__(8, 1, 1) __launch_bounds__(256, 1)
k_seq(const float* __restrict__ fcW, const float* __restrict__ fcb,
      const float* __restrict__ tfcW, const float* __restrict__ tfcb,
      const float* __restrict__ attW, const float* __restrict__ attb,
      const float* __restrict__ attc, float* __restrict__ out)
{
    extern __shared__ u64 WT_sm[];                 // 16384 u64 = 128 KB
    __shared__ __align__(16) float inbox[2][8][80];
    __shared__ __align__(16) float outbox[80];
    __shared__ __align__(16) float4 part4[8][32];
    __shared__ __align__(16) float4 partT4[8][32];
    __shared__ float WsO[128][11], WsT[128][11];
    __shared__ float fcw_t[320];
    __shared__ float tfc_s[32];
    __shared__ float attWs[10][10], attbs[10], attcs[10], fcbs[10];
    __shared__ float buf_s[8][10];
    __shared__ float prev_out_s[11];
    __shared__ float result_s[10];
    __shared__ float wsoft[8];
    __shared__ float hloc[32], thloc[32];
    __shared__ float prevT_s, tfcb_s;
    __shared__ __align__(8) u64 bars[2];

    const int t = threadIdx.x;
    uint32_t crank;
    asm("mov.u32 %0, %%cluster_ctarank;" : "=r"(crank));
    const int u = t & 31, wid = t >> 5, ci = (int)crank;

    u64 wO[64];
    {
        const u64* src = g_WO2 + (size_t)(ci * 8 + wid) * 64 * 32 + u;
#pragma unroll
        for (int i = 0; i < 64; i++) wO[i] = src[i * 32];
    }
    for (int i = t; i < 16384; i += 256) WT_sm[i] = g_WT2[(size_t)ci * 16384 + i];
    if (t < 128) {
#pragma unroll
        for (int k = 0; k < 11; k++) {
            WsO[t][k] = g_WseqO[(ci * 128 + t) * 11 + k];
            WsT[t][k] = g_WseqT[(ci * 128 + t) * 11 + k];
        }
    }
    for (int i = t; i < 320; i += 256) fcw_t[i] = fcW[(i >> 5) * 256 + ci * 32 + (i & 31)];
    if (t < 32)  tfc_s[t] = tfcW[ci * 32 + t];
    if (t < 100) attWs[t / 10][t % 10] = attW[t];
    if (t < 10)  { attbs[t] = attb[t]; attcs[t] = attc[t]; fcbs[t] = fcb[t]; result_s[t] = 0.f; }
    if (t < 11)  prev_out_s[t] = 0.f;
    if (t < 80)  buf_s[t / 10][t % 10] = 0.f;
    for (int i = t; i < 1280; i += 256) ((float*)inbox)[i] = 0.f;
    if (t < 80)  outbox[t] = 0.f;
    if (t == 0)  { tfcb_s = tfcb[0]; prevT_s = 0.f; }

    const uint32_t in_a  = (uint32_t)__cvta_generic_to_shared(&inbox[0][0][0]);
    const uint32_t out_a = (uint32_t)__cvta_generic_to_shared(&outbox[0]);
    const uint32_t bar_a = (uint32_t)__cvta_generic_to_shared(&bars[0]);
    if (t == 0) {
        mbar_init(bar_a, 1); mbar_init(bar_a + 8, 1);
        mbar_expect(bar_a + 8, 2560u);             // pre-arm for step 1
    }
    __syncthreads();
    cluster_sync_all();

    uint32_t rbin[8], rbbar[8];
#pragma unroll
    for (int r = 0; r < 8; r++) { rbin[r] = mapa_sh(in_a, r); rbbar[r] = mapa_sh(bar_a, r); }

    float cst = 0.f, tcst = 0.f;
    int ph0 = 0, ph1 = 0;
    float4 pvn = make_float4(0.f, 0.f, 0.f, 0.f), pvTn = pvn;
    if (wid == 0) pvn  = *(const float4*)(g_preO + ci * 128 + 4 * u);
    if (wid == 1) pvTn = *(const float4*)(g_preT + ci * 128 + 4 * u);

    for (int n = 0; n < NN; n++) {
        const int b = n >> 3;
        const bool start = (n & 7) == 0;
        const int q = n & 1;

        if (n > 0) {
            if (q) { mbar_wait(bar_a + 8, (uint32_t)ph1); ph1 ^= 1; }
            else   { mbar_wait(bar_a,     (uint32_t)ph0); ph0 ^= 1; }
            if (t == 0) bulk_wait_read();
        }

        // ---- phase 1: assemble prev outputs, matvecs, prefetch ----
        if (wid == 0 && n > 0) {
            if (u < 10) {
                float o = fcbs[u];
#pragma unroll
                for (int c = 0; c < 8; c++) o += inbox[q][c][64 + u];
                buf_s[(n - 1) & 7][u] = o;
                prev_out_s[u + 1] = o;
                if (ci == 0) out[(n - 1) * 11 + 1 + u] = o;
            } else if (u == 10) {
                if (((n - 1) & 7) == 0) {
                    float tv = tfcb_s;
#pragma unroll
                    for (int c = 0; c < 8; c++) tv += inbox[q][c][74];
                    prevT_s = tv;
                }
                prev_out_s[0] = prevT_s;
                if (ci == 0) out[(n - 1) * 11] = prevT_s;
            }
        }
        float4 pvc = make_float4(0.f, 0.f, 0.f, 0.f), pvTc = pvc;
        if (wid == 0) {
            pvc = pvn;
            int nn = (n + 1 < NN) ? n + 1 : n;
            pvn = *(const float4*)(g_preO + nn * 1024 + ci * 128 + 4 * u);
        }
        if (wid == 1 && start) {
            pvTc = pvTn;
            int bb = (b + 1 < NB) ? b + 1 : b;
            pvTn = *(const float4*)(g_preT + bb * 1024 + ci * 128 + 4 * u);
        }
        {
            const u64* hp8 = (const u64*)&inbox[q][wid][0];
            u64 a0 = 0, a1 = 0, a2 = 0, a3 = 0;
#pragma unroll
            for (int kp = 0; kp < 16; kp++) {
                u64 h2 = hp8[kp];
                ffma2(a0, wO[kp * 4 + 0], h2);
                ffma2(a1, wO[kp * 4 + 1], h2);
                ffma2(a2, wO[kp * 4 + 2], h2);
                ffma2(a3, wO[kp * 4 + 3], h2);
            }
            part4[wid][u] = make_float4(upk_sum(a0), upk_sum(a1), upk_sum(a2), upk_sum(a3));
        }
        if (start) {
            const u64* tp8 = (const u64*)&inbox[q][wid][32];
            u64 a0 = 0, a1 = 0, a2 = 0, a3 = 0;
#pragma unroll
            for (int kp = 0; kp < 16; kp++) {
                u64 h2 = tp8[kp];
                const u64* wt = WT_sm + (size_t)(wid * 16 + kp) * 128 + u;
                ffma2(a0, wt[0],  h2);
                ffma2(a1, wt[32], h2);
                ffma2(a2, wt[64], h2);
                ffma2(a3, wt[96], h2);
            }
            partT4[wid][u] = make_float4(upk_sum(a0), upk_sum(a1), upk_sum(a2), upk_sum(a3));
        }
        __syncthreads();

        // ---- phase 2 ----
        if (wid == 0) {
            float gi = pvc.x, gf = pvc.y, gg = pvc.z, go = pvc.w;
#pragma unroll
            for (int w = 0; w < 8; w++) {
                float4 p = part4[w][u];
                gi += p.x; gf += p.y; gg += p.z; go += p.w;
            }
#pragma unroll
            for (int k = 0; k < 11; k++) {
                float pk = prev_out_s[k];
                gi += WsO[u][k] * pk;
                gf += WsO[u + 32][k] * pk;
                gg += WsO[u + 64][k] * pk;
                go += WsO[u + 96][k] * pk;
            }
            float cn = sigm(gf) * cst + sigm(gi) * tanh_fast(gg);
            cst = cn;
            float hn = sigm(go) * tanh_fast(cn);
            hloc[u] = hn;
            outbox[u] = hn;
            __syncwarp();
            if (u < 10) {
                float p = 0.f;
#pragma unroll
                for (int k = 0; k < 32; k++) p += fcw_t[u * 32 + k] * hloc[k];
                outbox[64 + u] = p;
            }
        } else if (wid == 1 && start) {
            if (b > 0) {
                float sc = -1e30f;
                if (u < 8) {
                    sc = 0.f;
#pragma unroll
                    for (int j = 0; j < 10; j++) {
                        float a = attbs[j];
#pragma unroll
                        for (int k = 0; k < 10; k++) a += attWs[j][k] * buf_s[u][k];
                        sc += tanh_fast(a) * attcs[j];
                    }
                }
                float mx = sc;
#pragma unroll
                for (int off = 16; off; off >>= 1) mx = fmaxf(mx, __shfl_xor_sync(0xffffffffu, mx, off));
                float e = __expf(sc - mx);
                float sm = e;
#pragma unroll
                for (int off = 16; off; off >>= 1) sm += __shfl_xor_sync(0xffffffffu, sm, off);
                if (u < 8) wsoft[u] = e / sm;
                __syncwarp();
                if (u < 10) {
                    float r = 0.f;
#pragma unroll
                    for (int p = 0; p < 8; p++) r += wsoft[p] * buf_s[p][u];
                    result_s[u] = r;
                }
            } else if (u < 10) result_s[u] = 0.f;
            __syncwarp();
            float gi = pvTc.x, gf = pvTc.y, gg = pvTc.z, go = pvTc.w;
#pragma unroll
            for (int w = 0; w < 8; w++) {
                float4 p = partT4[w][u];
                gi += p.x; gf += p.y; gg += p.z; go += p.w;
            }
            {
                float p0 = prevT_s;
                gi += WsT[u][0] * p0;
                gf += WsT[u + 32][0] * p0;
                gg += WsT[u + 64][0] * p0;
                go += WsT[u + 96][0] * p0;
            }
#pragma unroll
            for (int k = 0; k < 10; k++) {
                float rk = result_s[k];
                gi += WsT[u][1 + k] * rk;
                gf += WsT[u + 32][1 + k] * rk;
                gg += WsT[u + 64][1 + k] * rk;
                go += WsT[u + 96][1 + k] * rk;
            }
            float cn = sigm(gf) * tcst + sigm(gi) * tanh_fast(gg);
            tcst = cn;
            float hn = sigm(go) * tanh_fast(cn);
            thloc[u] = hn;
            outbox[32 + u] = hn;
            __syncwarp();
            float v = tfc_s[u] * hn;
#pragma unroll
            for (int off = 16; off; off >>= 1) v += __shfl_down_sync(0xffffffffu, v, off);
            if (u == 0) outbox[74] = v;
        }
        __syncthreads();

        // ---- send: re-arm this step's mbar for n+2, then 8 bulk copies for n+1 ----
        if (t == 0) {
            mbar_expect(bar_a + (uint32_t)q * 8u, 2560u);
            uint32_t dq = (uint32_t)((n + 1) & 1);
#pragma unroll
            for (int r = 0; r < 8; r++)
                bulk_cluster(rbin[r] + (dq * 8u + (uint32_t)ci) * 320u, out_a, 320u, rbbar[r] + dq * 8u);
            bulk_commit();
        }
    }

    // ---- tail: flush outputs of step NN-1 (arrive in slot 0) ----
    mbar_wait(bar_a, (uint32_t)ph0);
    if (wid == 0 && ci == 0) {
        if (u < 10) {
            float o = fcbs[u];
#pragma unroll
            for (int c = 0; c < 8; c++) o += inbox[0][c][64 + u];
            out[(NN - 1) * 11 + 1 + u] = o;
        } else if (u == 10) {
            out[(NN - 1) * 11] = prevT_s;
        }
    }
    cluster_sync_all();
}

// ---------------- host launcher ----------------
extern "C" void kernel_launch(void* const* d_in, const int* in_sizes, int n_in,
                              void* d_out, int out_size)
{
    const float* note     = (const float*)d_in[0];
    const float* beat     = (const float*)d_in[1];
    const float* meas     = (const float*)d_in[2];
    const float* perf     = (const float*)d_in[3];
    const float* res      = (const float*)d_in[4];
    const float* sveW     = (const float*)d_in[5];
    const float* sveb     = (const float*)d_in[6];
    const float* psmWih   = (const float*)d_in[7];
    const float* psmWhh   = (const float*)d_in[8];
    const float* psmb     = (const float*)d_in[9];
    const float* mpfW     = (const float*)d_in[10];
    const float* mpfb     = (const float*)d_in[11];
    const float* attW     = (const float*)d_in[12];
    const float* attb     = (const float*)d_in[13];
    const float* attc     = (const float*)d_in[14];
    const float* tempoWih = (const float*)d_in[15];
    const float* tempoWhh = (const float*)d_in[16];
    const float* tempob   = (const float*)d_in[17];
    const float* tfcW     = (const float*)d_in[18];
    const float* tfcb     = (const float*)d_in[19];
    const float* outWih   = (const float*)d_in[20];
    const float* outWhh   = (const float*)d_in[21];
    const float* outb     = (const float*)d_in[22];
    const float* fcW      = (const float*)d_in[23];
    const float* fcb      = (const float*)d_in[24];

    float *Ppsm, *Hseq, *mps, *POn, *POb, *POm, *PTb, *PTm;
    cudaGetSymbolAddress((void**)&Ppsm, g_Ppsm);
    cudaGetSymbolAddress((void**)&Hseq, g_Hseq);
    cudaGetSymbolAddress((void**)&mps,  g_mps);
    cudaGetSymbolAddress((void**)&POn,  g_POn);
    cudaGetSymbolAddress((void**)&POb,  g_POb);
    cudaGetSymbolAddress((void**)&POm,  g_POm);
    cudaGetSymbolAddress((void**)&PTb,  g_PTb);
    cudaGetSymbolAddress((void**)&PTm,  g_PTm);

    static int smem_set = 0;
    if (!smem_set) {
        cudaFuncSetAttribute(k_seq, cudaFuncAttributeMaxDynamicSharedMemorySize, 131072);
        smem_set = 1;
    }

    k_style<<<1, 128>>>(perf, sveW, sveb);
    k_v0<<<1, 512>>>(psmWih, psmb);
    k_pack_w2<<<512, 256>>>(outWhh, tempoWhh);
    k_pack_wseq<<<44, 256>>>(outWih, tempoWih);
    k_pack_psm<<<256, 256>>>(psmWhh);

    k_gemm<<<dim3(8, 4), 256>>>(meas, 256, psmWih, 384, 128, Ppsm, 256, 512, 256, nullptr, 0);
    k_psm_seq<<<1, 512>>>();
    k_gemm<<<dim3(2, 4), 256>>>(Hseq, 128, mpfW, 128, 0, mps, 256, 128, 128, mpfb, 0);

    k_gemm<<<dim3(16, 128), 256>>>(note, 512, outWih, 1419, 0,    POn, NN, 1024, 512, nullptr, 0);
    k_gemm<<<dim3(16, 16),  256>>>(beat, 512, outWih, 1419, 512,  POb, NB, 1024, 512, nullptr, 0);
    k_gemm<<<dim3(16, 4),   256>>>(meas, 256, outWih, 1419, 1024, POm, NM, 1024, 256, outb,    0);
    k_gemm<<<dim3(16, 4),   256>>>(mps,  128, outWih, 1419, 1291, POm, NM, 1024, 128, nullptr, 1);

    k_gemm<<<dim3(16, 16), 256>>>(beat, 512, tempoWih, 915, 0,   PTb, NB, 1024, 512, tempob,  0);
    k_gemm<<<dim3(16, 16), 256>>>(res,  8,   tempoWih, 915, 769, PTb, NB, 1024, 8,   nullptr, 1);
    k_gemm<<<dim3(16, 4),  256>>>(meas, 256, tempoWih, 915, 512, PTm, NM, 1024, 256, nullptr, 0);
    k_gemm<<<dim3(16, 4),  256>>>(mps,  128, tempoWih, 915, 787, PTm, NM, 1024, 128, nullptr, 1);

    k_combine_O<<<NN * 4, 256>>>();
    k_combine_T<<<NB * 4, 256>>>();

    k_seq<<<8, 256, 131072>>>(fcW, fcb, tfcW, tfcb, attW, attb, attc, (float*)d_out);
}